// round 13
// baseline (speedup 1.0000x reference)
#include <cuda_runtime.h>
#include <cuda_bf16.h>
#include <stdint.h>

// Problem constants
#define K_CB   4096
#define HID    1024
#define VQd    64
#define Dd     768
#define Bb     8
#define Tt     2048
#define NTOK   (Bb*Tt)
#define L2b    12
#define N_MID  4
#define EPS_N  1e-6f
#define EPS_BN 1e-5f

#define CCAP   256
#define CTH    0.03f
#define CPITCH 68

// ---------------- scratch (device globals) ----------------
__device__ float g_x[K_CB * HID];
__device__ float g_y[K_CB * HID];
__device__ float g_embed[K_CB * VQd];
__device__ float g_enorm2[K_CB];
__device__ float g_h[NTOK * VQd];
__device__ float g_esel[NTOK * VQd];
__device__ float g_stats[N_MID * 2 * HID];
__device__ int g_ccnt[NTOK];
__device__ int g_cand[(size_t)NTOK * CCAP];

// ---------------- helpers ----------------
static __device__ __forceinline__ void mma_tf32(float* c, const uint32_t* a,
                                                const uint32_t* b) {
    asm volatile(
        "mma.sync.aligned.m16n8k8.row.col.f32.tf32.tf32.f32 "
        "{%0,%1,%2,%3}, {%4,%5,%6,%7}, {%8,%9}, {%0,%1,%2,%3};"
        : "+f"(c[0]), "+f"(c[1]), "+f"(c[2]), "+f"(c[3])
        : "r"(a[0]), "r"(a[1]), "r"(a[2]), "r"(a[3]), "r"(b[0]), "r"(b[1]));
}
static __device__ __forceinline__ unsigned fmap(float s) {
    unsigned u = __float_as_uint(s);
    return (u & 0x80000000u) ? ~u : (u | 0x80000000u);
}
static __device__ __forceinline__ float funmap(unsigned v) {
    unsigned u = (v & 0x80000000u) ? (v ^ 0x80000000u) : ~v;
    return __uint_as_float(u);
}

// ---------------- small utility kernels ----------------
__global__ void zero_all_stats_kernel() {
    int i = blockIdx.x * 256 + threadIdx.x;
    if (i < N_MID * 2 * HID) g_stats[i] = 0.f;
}

// ---------------- layer 0 (R1-proven) ----------------
__global__ __launch_bounds__(256) void layer0_kernel(
    const float* __restrict__ W, const float* __restrict__ bias,
    const float* __restrict__ gamma, const float* __restrict__ beta,
    float* __restrict__ X)
{
    int f = blockIdx.x * 256 + threadIdx.x;
    int k0 = blockIdx.y * 16;
    float w[L2b];
    float sw = 0.f, sw2 = 0.f;
#pragma unroll
    for (int j = 0; j < L2b; j++) {
        w[j] = W[f * L2b + j];
        sw += w[j]; sw2 += w[j] * w[j];
    }
    float b = bias[f];
    float m = b + 0.5f * sw;
    float v = 0.25f * sw2;
    float rstd = rsqrtf(v + EPS_BN);
    float ga = gamma[f] * rstd;
    float be = beta[f];
#pragma unroll 4
    for (int kk = 0; kk < 16; kk++) {
        int k = k0 + kk;
        float y = b;
#pragma unroll
        for (int j = 0; j < L2b; j++)
            if ((k >> (11 - j)) & 1) y += w[j];
        float o = (y - m) * ga + be;
        X[k * HID + f] = fmaxf(o, 0.f);
    }
}

// ---------------- BN normalize + ReLU (R9-proven) ----------------
__global__ __launch_bounds__(256) void bn_norm_relu_kernel(
    const float* __restrict__ Y, const float* __restrict__ gamma,
    const float* __restrict__ beta, float* __restrict__ X, int layer)
{
    const float* st = &g_stats[layer * 2 * HID];
    int base = blockIdx.x * 1024 + threadIdx.x;
#pragma unroll
    for (int u = 0; u < 4; u++) {
        int i4 = base + u * 256;
        int f0 = (i4 * 4) & (HID - 1);
        float4 y = ((const float4*)Y)[i4];
        float yv[4] = { y.x, y.y, y.z, y.w };
        float out[4];
#pragma unroll
        for (int j = 0; j < 4; j++) {
            int f = f0 + j;
            float m = st[f] * (1.f / K_CB);
            float var = st[HID + f] * (1.f / K_CB) - m * m;
            float o = (yv[j] - m) * rsqrtf(var + EPS_BN) * gamma[f] + beta[f];
            out[j] = fmaxf(o, 0.f);
        }
        ((float4*)X)[i4] = make_float4(out[0], out[1], out[2], out[3]);
    }
}

// ---------------- fp32 NT GEMM, double-buffered BK=16 + fused BN stats (R9-proven) ----------------
__global__ __launch_bounds__(256, 2) void gemm128_nt(
    const float* __restrict__ A, const float* __restrict__ B,
    const float* __restrict__ bias, float* __restrict__ C,
    int M, int N, int K, int layer)
{
    __shared__ float As[2][16][132];
    __shared__ float Bs[2][16][132];
    const int tid = threadIdx.x;
    const int tx = tid & 15, ty = tid >> 4;
    const int m0 = blockIdx.y * 128, n0 = blockIdx.x * 128;
    const int lr = tid >> 1;
    const int lc = (tid & 1) << 3;
    const float* Ag = A + (size_t)(m0 + lr) * K + lc;
    const float* Bg = B + (size_t)(n0 + lr) * K + lc;

    float acc[8][8];
#pragma unroll
    for (int i = 0; i < 8; i++)
#pragma unroll
        for (int j = 0; j < 8; j++) acc[i][j] = 0.f;

    float4 ra0 = *(const float4*)(Ag);
    float4 ra1 = *(const float4*)(Ag + 4);
    float4 rb0 = *(const float4*)(Bg);
    float4 rb1 = *(const float4*)(Bg + 4);

    const int NC = K >> 4;
    for (int c = 0; c < NC; c++) {
        const int s = c & 1;
        As[s][lc + 0][lr] = ra0.x; As[s][lc + 1][lr] = ra0.y;
        As[s][lc + 2][lr] = ra0.z; As[s][lc + 3][lr] = ra0.w;
        As[s][lc + 4][lr] = ra1.x; As[s][lc + 5][lr] = ra1.y;
        As[s][lc + 6][lr] = ra1.z; As[s][lc + 7][lr] = ra1.w;
        Bs[s][lc + 0][lr] = rb0.x; Bs[s][lc + 1][lr] = rb0.y;
        Bs[s][lc + 2][lr] = rb0.z; Bs[s][lc + 3][lr] = rb0.w;
        Bs[s][lc + 4][lr] = rb1.x; Bs[s][lc + 5][lr] = rb1.y;
        Bs[s][lc + 6][lr] = rb1.z; Bs[s][lc + 7][lr] = rb1.w;
        __syncthreads();
        if (c + 1 < NC) {
            const int kn = (c + 1) << 4;
            ra0 = *(const float4*)(Ag + kn);
            ra1 = *(const float4*)(Ag + kn + 4);
            rb0 = *(const float4*)(Bg + kn);
            rb1 = *(const float4*)(Bg + kn + 4);
        }
#pragma unroll
        for (int kk = 0; kk < 16; kk++) {
            float ar[8], br[8];
            *(float4*)&ar[0] = *(const float4*)&As[s][kk][ty * 4];
            *(float4*)&ar[4] = *(const float4*)&As[s][kk][64 + ty * 4];
            *(float4*)&br[0] = *(const float4*)&Bs[s][kk][tx * 4];
            *(float4*)&br[4] = *(const float4*)&Bs[s][kk][64 + tx * 4];
#pragma unroll
            for (int i = 0; i < 8; i++)
#pragma unroll
                for (int j = 0; j < 8; j++)
                    acc[i][j] = fmaf(ar[i], br[j], acc[i][j]);
        }
    }

    float cs[8], cs2[8];
#pragma unroll
    for (int j8 = 0; j8 < 8; j8++) { cs[j8] = 0.f; cs2[j8] = 0.f; }

#pragma unroll
    for (int ih = 0; ih < 2; ih++) {
#pragma unroll
        for (int i = 0; i < 4; i++) {
            int r = m0 + ih * 64 + ty * 4 + i;
            float* Crow = C + (size_t)r * N + n0;
#pragma unroll
            for (int jh = 0; jh < 2; jh++) {
                int cb = jh * 64 + tx * 4;
                float4 v;
                v.x = acc[ih * 4 + i][jh * 4 + 0] + bias[n0 + cb + 0];
                v.y = acc[ih * 4 + i][jh * 4 + 1] + bias[n0 + cb + 1];
                v.z = acc[ih * 4 + i][jh * 4 + 2] + bias[n0 + cb + 2];
                v.w = acc[ih * 4 + i][jh * 4 + 3] + bias[n0 + cb + 3];
                *(float4*)(Crow + cb) = v;
                if (layer >= 0) {
                    cs[jh * 4 + 0] += v.x;  cs2[jh * 4 + 0] += v.x * v.x;
                    cs[jh * 4 + 1] += v.y;  cs2[jh * 4 + 1] += v.y * v.y;
                    cs[jh * 4 + 2] += v.z;  cs2[jh * 4 + 2] += v.z * v.z;
                    cs[jh * 4 + 3] += v.w;  cs2[jh * 4 + 3] += v.w * v.w;
                }
            }
        }
    }
    if (layer >= 0) {
        __syncthreads();
        float* sst = &As[0][0][0];
        if (tid < 256) sst[tid] = 0.f;
        __syncthreads();
#pragma unroll
        for (int jh = 0; jh < 2; jh++)
#pragma unroll
            for (int j = 0; j < 4; j++) {
                int cl = jh * 64 + tx * 4 + j;
                atomicAdd(&sst[cl], cs[jh * 4 + j]);
                atomicAdd(&sst[128 + cl], cs2[jh * 4 + j]);
            }
        __syncthreads();
        if (tid < 128) {
            float* gs = &g_stats[layer * 2 * HID];
            atomicAdd(&gs[n0 + tid], sst[tid]);
            atomicAdd(&gs[HID + n0 + tid], sst[128 + tid]);
        }
    }
}

// ---------------- 64x64 NT GEMM (R1-proven, output layer) ----------------
__global__ __launch_bounds__(256) void gemm64_nt(
    const float* __restrict__ A, const float* __restrict__ B,
    const float* __restrict__ bias, float* __restrict__ C,
    int M, int N, int K)
{
    __shared__ float As[8][68];
    __shared__ float Bs[8][68];
    const int tid = threadIdx.x;
    const int tx = tid & 15, ty = tid >> 4;
    const int m0 = blockIdx.y * 64, n0 = blockIdx.x * 64;
    float acc[4][4];
#pragma unroll
    for (int i = 0; i < 4; i++)
#pragma unroll
        for (int j = 0; j < 4; j++) acc[i][j] = 0.f;

    const int half = tid >> 7;
    const int lt = tid & 127;
    const int lr = lt >> 1;
    const int lcv = (lt & 1) << 2;
    const float* G = half ? (B + (size_t)(n0 + lr) * K + lcv)
                          : (A + (size_t)(m0 + lr) * K + lcv);

    for (int k0 = 0; k0 < K; k0 += 8) {
        float4 g4 = *(const float4*)(G + k0);
        if (half == 0) {
            As[lcv + 0][lr] = g4.x; As[lcv + 1][lr] = g4.y; As[lcv + 2][lr] = g4.z; As[lcv + 3][lr] = g4.w;
        } else {
            Bs[lcv + 0][lr] = g4.x; Bs[lcv + 1][lr] = g4.y; Bs[lcv + 2][lr] = g4.z; Bs[lcv + 3][lr] = g4.w;
        }
        __syncthreads();
#pragma unroll
        for (int kk = 0; kk < 8; kk++) {
            float ar[4], br[4];
            *(float4*)&ar[0] = *(const float4*)&As[kk][ty * 4];
            *(float4*)&br[0] = *(const float4*)&Bs[kk][tx * 4];
#pragma unroll
            for (int i = 0; i < 4; i++)
#pragma unroll
                for (int j = 0; j < 4; j++)
                    acc[i][j] = fmaf(ar[i], br[j], acc[i][j]);
        }
        __syncthreads();
    }
#pragma unroll
    for (int i = 0; i < 4; i++) {
        int r = m0 + ty * 4 + i;
        float4 v;
        v.x = acc[i][0] + bias[n0 + tx * 4 + 0];
        v.y = acc[i][1] + bias[n0 + tx * 4 + 1];
        v.z = acc[i][2] + bias[n0 + tx * 4 + 2];
        v.w = acc[i][3] + bias[n0 + tx * 4 + 3];
        *(float4*)(C + (size_t)r * N + n0 + tx * 4) = v;
    }
}

// ---------------- embed L2 norm + ||e||^2 (R1-proven) ----------------
__global__ __launch_bounds__(256) void embed_norm_kernel(const float* __restrict__ Eraw)
{
    int row = blockIdx.x * 8 + (threadIdx.x >> 5);
    int lane = threadIdx.x & 31;
    float v0 = Eraw[row * VQd + lane];
    float v1 = Eraw[row * VQd + 32 + lane];
    float s = v0 * v0 + v1 * v1;
#pragma unroll
    for (int off = 16; off; off >>= 1) s += __shfl_xor_sync(0xffffffffu, s, off);
    float norm = sqrtf(s);
    float sc = 1.f / (norm + EPS_N);
    g_embed[row * VQd + lane] = v0 * sc;
    g_embed[row * VQd + 32 + lane] = v1 * sc;
    if (lane == 0) g_enorm2[row] = s * sc * sc;
}

// ---------------- hidden projection + L2 normalize (R1-proven) ----------------
__global__ __launch_bounds__(256) void hproj_kernel(
    const float* __restrict__ Hin, const float* __restrict__ Pw,
    const float* __restrict__ Pb, float* __restrict__ Hout)
{
    __shared__ float Ash[32][132];
    __shared__ float Wsh[32][65];
    const int tid = threadIdx.x;
    const int b = blockIdx.y;
    const int t0 = blockIdx.x * 128;
    const int tx = tid & 15, ty = tid >> 4;
    float acc[8][4];
#pragma unroll
    for (int i = 0; i < 8; i++)
#pragma unroll
        for (int j = 0; j < 4; j++) acc[i][j] = 0.f;

    const int lt = tid & 127;
    const int ldr = tid >> 7;
    const int wv = tid >> 5;
    const int wd = tid & 31;

    for (int d0 = 0; d0 < Dd; d0 += 32) {
#pragma unroll
        for (int dd = ldr; dd < 32; dd += 2)
            Ash[dd][lt] = Hin[(size_t)(b * Dd + d0 + dd) * Tt + t0 + lt];
#pragma unroll
        for (int vv = wv; vv < 64; vv += 8)
            Wsh[wd][vv] = Pw[vv * Dd + d0 + wd];
        __syncthreads();
#pragma unroll
        for (int kk = 0; kk < 32; kk++) {
            float ar[8], br[4];
            *(float4*)&ar[0] = *(const float4*)&Ash[kk][ty * 4];
            *(float4*)&ar[4] = *(const float4*)&Ash[kk][64 + ty * 4];
#pragma unroll
            for (int j = 0; j < 4; j++) br[j] = Wsh[kk][tx * 4 + j];
#pragma unroll
            for (int i = 0; i < 8; i++)
#pragma unroll
                for (int j = 0; j < 4; j++)
                    acc[i][j] = fmaf(ar[i], br[j], acc[i][j]);
        }
        __syncthreads();
    }
    float bb[4];
#pragma unroll
    for (int j = 0; j < 4; j++) bb[j] = Pb[tx * 4 + j];
#pragma unroll
    for (int i = 0; i < 8; i++) {
        float hv[4]; float ssq = 0.f;
#pragma unroll
        for (int j = 0; j < 4; j++) { hv[j] = acc[i][j] + bb[j]; ssq += hv[j] * hv[j]; }
#pragma unroll
        for (int off = 8; off; off >>= 1) ssq += __shfl_xor_sync(0xffffffffu, ssq, off, 16);
        float sc = 1.f / (sqrtf(ssq) + EPS_N);
        int t = t0 + ((i < 4) ? ty * 4 + i : 64 + ty * 4 + (i - 4));
        float4 o = make_float4(hv[0] * sc, hv[1] * sc, hv[2] * sc, hv[3] * sc);
        *(float4*)&Hout[(size_t)(b * Tt + t) * VQd + tx * 4] = o;
    }
}

// ---------------- coarse tf32 score pass + candidate emission (R7/R10-proven) ----------------
__global__ __launch_bounds__(256) void coarse_kernel()
{
    extern __shared__ float smc[];
    float* sA = smc;
    float* sB = smc + 128 * CPITCH;
    float* e2sm = smc + 2 * 128 * CPITCH;
    __shared__ unsigned smax[128];
    __shared__ int cnt[128];

    const int tid = threadIdx.x;
    const int lane = tid & 31, wid = tid >> 5;
    const int wm = wid >> 2, wn = wid & 3;
    const int g = lane >> 2, tig = lane & 3;
    const int m0 = blockIdx.x * 128;

    for (int i = tid; i < 2048; i += 256) {
        int r = i >> 4, q = i & 15;
        *(float4*)&sA[r * CPITCH + q * 4] = *(const float4*)&g_h[(size_t)(m0 + r) * VQd + q * 4];
    }
    if (tid < 128) { smax[tid] = 0u; cnt[tid] = 0; }
    __syncthreads();

    for (int ch = 0; ch < 32; ch++) {
        const int n0 = ch * 128;
        for (int i = tid; i < 2048; i += 256) {
            int r = i >> 4, q = i & 15;
            *(float4*)&sB[r * CPITCH + q * 4] = *(const float4*)&g_embed[(size_t)(n0 + r) * VQd + q * 4];
        }
        if (tid < 128) e2sm[tid] = g_enorm2[n0 + tid];
        __syncthreads();

        float acc[4][4][4];
#pragma unroll
        for (int mt = 0; mt < 4; mt++)
#pragma unroll
            for (int nt = 0; nt < 4; nt++)
#pragma unroll
                for (int q = 0; q < 4; q++) acc[mt][nt][q] = 0.f;

#pragma unroll
        for (int ks = 0; ks < 8; ks++) {
            const int kb = ks * 8;
            uint32_t a[4][4];
#pragma unroll
            for (int mt = 0; mt < 4; mt++) {
                const uint32_t* pa = (const uint32_t*)&sA[(wm * 64 + mt * 16 + g) * CPITCH + kb + tig];
                a[mt][0] = pa[0];
                a[mt][1] = pa[8 * CPITCH];
                a[mt][2] = pa[4];
                a[mt][3] = pa[8 * CPITCH + 4];
            }
            uint32_t b[4][2];
#pragma unroll
            for (int nt = 0; nt < 4; nt++) {
                const uint32_t* pb = (const uint32_t*)&sB[(wn * 32 + nt * 8 + g) * CPITCH + kb + tig];
                b[nt][0] = pb[0];
                b[nt][1] = pb[4];
            }
#pragma unroll
            for (int mt = 0; mt < 4; mt++)
#pragma unroll
                for (int nt = 0; nt < 4; nt++)
                    mma_tf32(acc[mt][nt], a[mt], b[nt]);
        }

        float rmax[4][2];
#pragma unroll
        for (int mt = 0; mt < 4; mt++) {
            rmax[mt][0] = -3.4e38f; rmax[mt][1] = -3.4e38f;
#pragma unroll
            for (int nt = 0; nt < 4; nt++) {
                int col0 = wn * 32 + nt * 8 + 2 * tig;
                float e20 = e2sm[col0], e21 = e2sm[col0 + 1];
                float s0 = 2.f * acc[mt][nt][0] - e20;
                float s1 = 2.f * acc[mt][nt][1] - e21;
                float s2 = 2.f * acc[mt][nt][2] - e20;
                float s3 = 2.f * acc[mt][nt][3] - e21;
                rmax[mt][0] = fmaxf(rmax[mt][0], fmaxf(s0, s1));
                rmax[mt][1] = fmaxf(rmax[mt][1], fmaxf(s2, s3));
            }
        }
#pragma unroll
        for (int off = 1; off <= 2; off <<= 1)
#pragma unroll
            for (int mt = 0; mt < 4; mt++)
#pragma unroll
                for (int h = 0; h < 2; h++)
                    rmax[mt][h] = fmaxf(rmax[mt][h], __shfl_xor_sync(0xffffffffu, rmax[mt][h], off));
        if (tig == 0) {
#pragma unroll
            for (int mt = 0; mt < 4; mt++) {
                atomicMax(&smax[wm * 64 + mt * 16 + g], fmap(rmax[mt][0]));
                atomicMax(&smax[wm * 64 + mt * 16 + g + 8], fmap(rmax[mt][1]));
            }
        }
        __syncthreads();

#pragma unroll
        for (int mt = 0; mt < 4; mt++) {
            int rr0 = wm * 64 + mt * 16 + g;
            float th0 = funmap(smax[rr0]) - CTH;
            float th1 = funmap(smax[rr0 + 8]) - CTH;
#pragma unroll
            for (int nt = 0; nt < 4; nt++) {
                int col0 = wn * 32 + nt * 8 + 2 * tig;
                float e20 = e2sm[col0], e21 = e2sm[col0 + 1];
                float s0 = 2.f * acc[mt][nt][0] - e20;
                float s1 = 2.f * acc[mt][nt][1] - e21;
                float s2 = 2.f * acc[mt][nt][2] - e20;
                float s3 = 2.f * acc[mt][nt][3] - e21;
                if (s0 >= th0) { int p = atomicAdd(&cnt[rr0], 1); if (p < CCAP) g_cand[(size_t)(m0 + rr0) * CCAP + p] = n0 + col0; }
                if (s1 >= th0) { int p = atomicAdd(&cnt[rr0], 1); if (p < CCAP) g_cand[(size_t)(m0 + rr0) * CCAP + p] = n0 + col0 + 1; }
                if (s2 >= th1) { int p = atomicAdd(&cnt[rr0 + 8], 1); if (p < CCAP) g_cand[(size_t)(m0 + rr0 + 8) * CCAP + p] = n0 + col0; }
                if (s3 >= th1) { int p = atomicAdd(&cnt[rr0 + 8], 1); if (p < CCAP) g_cand[(size_t)(m0 + rr0 + 8) * CCAP + p] = n0 + col0 + 1; }
            }
        }
        __syncthreads();
    }
    if (tid < 128) g_ccnt[m0 + tid] = cnt[tid];
}

// ---------------- exact rescore + fused gather (scores bit-identical to R1) ----------------
__global__ __launch_bounds__(256) void rescore_gather_kernel(
    const int* __restrict__ attn, float* __restrict__ out_codes, int write_codes)
{
    __shared__ float sh[8][VQd];
    const int tid = threadIdx.x;
    const int lane = tid & 31, wid = tid >> 5;
    const int token = blockIdx.x * 8 + wid;

    sh[wid][lane] = g_h[(size_t)token * VQd + lane];
    sh[wid][lane + 32] = g_h[(size_t)token * VQd + lane + 32];
    __syncwarp();

    int cnt = g_ccnt[token];
    unsigned long long best = 0ull;

    if (cnt > 0 && cnt <= CCAP) {
        for (int ci = lane; ci < cnt; ci += 32) {
            int code = g_cand[(size_t)token * CCAP + ci];
            float acc = 0.f;
            const float* e = &g_embed[(size_t)code * VQd];
#pragma unroll
            for (int q = 0; q < 16; q++) {
                float4 ev = *(const float4*)&e[q * 4];
                acc = fmaf(sh[wid][q * 4 + 0], ev.x, acc);
                acc = fmaf(sh[wid][q * 4 + 1], ev.y, acc);
                acc = fmaf(sh[wid][q * 4 + 2], ev.z, acc);
                acc = fmaf(sh[wid][q * 4 + 3], ev.w, acc);
            }
            float s = 2.f * acc - g_enorm2[code];
            unsigned u = __float_as_uint(s);
            u = (u & 0x80000000u) ? ~u : (u | 0x80000000u);
            unsigned long long key =
                ((unsigned long long)u << 32) | (unsigned)(0xFFFFFFFFu - (unsigned)code);
            best = (key > best) ? key : best;
        }
    } else {
        for (int code = lane; code < K_CB; code += 32) {
            float acc = 0.f;
            const float* e = &g_embed[(size_t)code * VQd];
#pragma unroll
            for (int q = 0; q < 16; q++) {
                float4 ev = *(const float4*)&e[q * 4];
                acc = fmaf(sh[wid][q * 4 + 0], ev.x, acc);
                acc = fmaf(sh[wid][q * 4 + 1], ev.y, acc);
                acc = fmaf(sh[wid][q * 4 + 2], ev.z, acc);
                acc = fmaf(sh[wid][q * 4 + 3], ev.w, acc);
            }
            float s = 2.f * acc - g_enorm2[code];
            unsigned u = __float_as_uint(s);
            u = (u & 0x80000000u) ? ~u : (u | 0x80000000u);
            unsigned long long key =
                ((unsigned long long)u << 32) | (unsigned)(0xFFFFFFFFu - (unsigned)code);
            best = (key > best) ? key : best;
        }
    }
#pragma unroll
    for (int off = 16; off; off >>= 1) {
        unsigned long long o = __shfl_xor_sync(0xffffffffu, best, off);
        best = (o > best) ? o : best;
    }
    // every lane now holds the winning key -> fused gather
    int code = (int)(0xFFFFFFFFu - (unsigned)(best & 0xFFFFFFFFull));
    int msk = (attn[token] == 1);
    const float* e = &g_embed[(size_t)code * VQd];
    float v0 = msk ? e[lane] : 0.f;
    float v1 = msk ? e[lane + 32] : 0.f;
    g_esel[(size_t)token * VQd + lane] = v0;
    g_esel[(size_t)token * VQd + lane + 32] = v1;
    if (write_codes && lane == 0)
        out_codes[token] = msk ? (float)code : 0.f;
}

// ---------------- host launcher ----------------
extern "C" void kernel_launch(void* const* d_in, const int* in_sizes, int n_in,
                              void* d_out, int out_size)
{
    const float* h_in     = (const float*)d_in[0];
    const int*   attn     = (const int*)  d_in[1];
    const float* proj_w   = (const float*)d_in[2];
    const float* proj_b   = (const float*)d_in[3];
    const float* inv_w    = (const float*)d_in[4];
    const float* inv_b    = (const float*)d_in[5];
    const float* mlp_w_in = (const float*)d_in[6];
    const float* mlp_b_in = (const float*)d_in[7];
    const float* w_mid    = (const float*)d_in[8];
    const float* b_mid    = (const float*)d_in[9];
    const float* w_out    = (const float*)d_in[10];
    const float* b_out    = (const float*)d_in[11];
    const float* gamma    = (const float*)d_in[12];
    const float* beta     = (const float*)d_in[13];
    float* out = (float*)d_out;

    void *px_, *py_, *pes_, *ph_;
    cudaGetSymbolAddress(&px_, g_x);
    cudaGetSymbolAddress(&py_, g_y);
    cudaGetSymbolAddress(&pes_, g_esel);
    cudaGetSymbolAddress(&ph_, g_h);
    float* px = (float*)px_;
    float* py = (float*)py_;
    float* pes = (float*)pes_;
    float* ph = (float*)ph_;

    const int COARSE_SMEM = (2 * 128 * CPITCH + 128) * 4;
    cudaFuncSetAttribute(coarse_kernel,
                         cudaFuncAttributeMaxDynamicSharedMemorySize, COARSE_SMEM);

    // 0) zero all per-layer BN stats once
    zero_all_stats_kernel<<<(N_MID * 2 * HID + 255) / 256, 256>>>();

    // 1) codebook MLP (fp32, chains bit-identical; stats fused into GEMM epilogue)
    layer0_kernel<<<dim3(4, 256), 256>>>(mlp_w_in, mlp_b_in, gamma, beta, px);
    for (int i = 0; i < N_MID; i++) {
        gemm128_nt<<<dim3(HID / 128, K_CB / 128), 256>>>(
            px, w_mid + (size_t)i * HID * HID, b_mid + i * HID, py, K_CB, HID, HID, i);
        bn_norm_relu_kernel<<<(K_CB * HID / 4) / 1024, 256>>>(
            py, gamma + (i + 1) * HID, beta + (i + 1) * HID, px, i);
    }
    gemm64_nt<<<dim3(1, K_CB / 64), 256>>>(px, w_out, b_out, py, K_CB, VQd, HID);
    embed_norm_kernel<<<K_CB / 8, 256>>>(py);

    // 2) hidden projection + L2 normalize
    hproj_kernel<<<dim3(Tt / 128, Bb), 256>>>(h_in, proj_w, proj_b, ph);

    // 3) certified two-pass argmax + fused gather
    coarse_kernel<<<NTOK / 128, 256, COARSE_SMEM>>>();
    int write_codes = (out_size >= NTOK * Dd + NTOK) ? 1 : 0;
    rescore_gather_kernel<<<NTOK / 8, 256>>>(attn, out + (size_t)NTOK * Dd, write_codes);

    // 4) inverse projection straight into d_out (no stats)
    gemm128_nt<<<dim3(Dd / 128, NTOK / 128), 256>>>(
        pes, inv_w, inv_b, out, NTOK, Dd, VQd, -1);
}

// round 14
// speedup vs baseline: 1.5908x; 1.5908x over previous
#include <cuda_runtime.h>
#include <cuda_bf16.h>
#include <stdint.h>

// Problem constants
#define K_CB   4096
#define HID    1024
#define VQd    64
#define Dd     768
#define Bb     8
#define Tt     2048
#define NTOK   (Bb*Tt)
#define L2b    12
#define N_MID  4
#define EPS_N  1e-6f
#define EPS_BN 1e-5f

#define CCAP   256
#define CTH    0.03f
#define CPITCH 68

// ---------------- scratch (device globals) ----------------
__device__ float g_x[K_CB * HID];
__device__ float g_y[K_CB * HID];
__device__ float g_embed[K_CB * VQd];
__device__ float g_enorm2[K_CB];
__device__ float g_h[NTOK * VQd];
__device__ float g_esel[NTOK * VQd];
__device__ float g_stats[N_MID * 2 * HID];    // per-layer (sum, sumsq)
__device__ unsigned long long g_best[NTOK];
__device__ int g_ccnt[NTOK];
__device__ int g_cand[(size_t)NTOK * CCAP];

// ---------------- helpers ----------------
static __device__ __forceinline__ void mma_tf32(float* c, const uint32_t* a,
                                                const uint32_t* b) {
    asm volatile(
        "mma.sync.aligned.m16n8k8.row.col.f32.tf32.tf32.f32 "
        "{%0,%1,%2,%3}, {%4,%5,%6,%7}, {%8,%9}, {%0,%1,%2,%3};"
        : "+f"(c[0]), "+f"(c[1]), "+f"(c[2]), "+f"(c[3])
        : "r"(a[0]), "r"(a[1]), "r"(a[2]), "r"(a[3]), "r"(b[0]), "r"(b[1]));
}
static __device__ __forceinline__ unsigned fmap(float s) {
    unsigned u = __float_as_uint(s);
    return (u & 0x80000000u) ? ~u : (u | 0x80000000u);
}
static __device__ __forceinline__ float funmap(unsigned v) {
    unsigned u = (v & 0x80000000u) ? (v ^ 0x80000000u) : ~v;
    return __uint_as_float(u);
}

// ---------------- small utility kernels ----------------
__global__ void zero_all_stats_kernel() {
    int i = blockIdx.x * 256 + threadIdx.x;
    if (i < N_MID * 2 * HID) g_stats[i] = 0.f;
}

// ---------------- layer 0 (R1-proven) ----------------
__global__ __launch_bounds__(256) void layer0_kernel(
    const float* __restrict__ W, const float* __restrict__ bias,
    const float* __restrict__ gamma, const float* __restrict__ beta,
    float* __restrict__ X)
{
    int f = blockIdx.x * 256 + threadIdx.x;
    int k0 = blockIdx.y * 16;
    float w[L2b];
    float sw = 0.f, sw2 = 0.f;
#pragma unroll
    for (int j = 0; j < L2b; j++) {
        w[j] = W[f * L2b + j];
        sw += w[j]; sw2 += w[j] * w[j];
    }
    float b = bias[f];
    float m = b + 0.5f * sw;
    float v = 0.25f * sw2;
    float rstd = rsqrtf(v + EPS_BN);
    float ga = gamma[f] * rstd;
    float be = beta[f];
#pragma unroll 4
    for (int kk = 0; kk < 16; kk++) {
        int k = k0 + kk;
        float y = b;
#pragma unroll
        for (int j = 0; j < L2b; j++)
            if ((k >> (11 - j)) & 1) y += w[j];
        float o = (y - m) * ga + be;
        X[k * HID + f] = fmaxf(o, 0.f);
    }
}

// ---------------- BN normalize + ReLU (R9-proven) ----------------
__global__ __launch_bounds__(256) void bn_norm_relu_kernel(
    const float* __restrict__ Y, const float* __restrict__ gamma,
    const float* __restrict__ beta, float* __restrict__ X, int layer)
{
    const float* st = &g_stats[layer * 2 * HID];
    int base = blockIdx.x * 1024 + threadIdx.x;
#pragma unroll
    for (int u = 0; u < 4; u++) {
        int i4 = base + u * 256;
        int f0 = (i4 * 4) & (HID - 1);
        float4 y = ((const float4*)Y)[i4];
        float yv[4] = { y.x, y.y, y.z, y.w };
        float out[4];
#pragma unroll
        for (int j = 0; j < 4; j++) {
            int f = f0 + j;
            float m = st[f] * (1.f / K_CB);
            float var = st[HID + f] * (1.f / K_CB) - m * m;
            float o = (yv[j] - m) * rsqrtf(var + EPS_BN) * gamma[f] + beta[f];
            out[j] = fmaxf(o, 0.f);
        }
        ((float4*)X)[i4] = make_float4(out[0], out[1], out[2], out[3]);
    }
}

// ---------------- fp32 NT GEMM, double-buffered BK=16 + fused BN stats (R9-proven) ----------------
__global__ __launch_bounds__(256, 2) void gemm128_nt(
    const float* __restrict__ A, const float* __restrict__ B,
    const float* __restrict__ bias, float* __restrict__ C,
    int M, int N, int K, int layer)
{
    __shared__ float As[2][16][132];
    __shared__ float Bs[2][16][132];
    const int tid = threadIdx.x;
    const int tx = tid & 15, ty = tid >> 4;
    const int m0 = blockIdx.y * 128, n0 = blockIdx.x * 128;
    const int lr = tid >> 1;
    const int lc = (tid & 1) << 3;
    const float* Ag = A + (size_t)(m0 + lr) * K + lc;
    const float* Bg = B + (size_t)(n0 + lr) * K + lc;

    float acc[8][8];
#pragma unroll
    for (int i = 0; i < 8; i++)
#pragma unroll
        for (int j = 0; j < 8; j++) acc[i][j] = 0.f;

    float4 ra0 = *(const float4*)(Ag);
    float4 ra1 = *(const float4*)(Ag + 4);
    float4 rb0 = *(const float4*)(Bg);
    float4 rb1 = *(const float4*)(Bg + 4);

    const int NC = K >> 4;
    for (int c = 0; c < NC; c++) {
        const int s = c & 1;
        As[s][lc + 0][lr] = ra0.x; As[s][lc + 1][lr] = ra0.y;
        As[s][lc + 2][lr] = ra0.z; As[s][lc + 3][lr] = ra0.w;
        As[s][lc + 4][lr] = ra1.x; As[s][lc + 5][lr] = ra1.y;
        As[s][lc + 6][lr] = ra1.z; As[s][lc + 7][lr] = ra1.w;
        Bs[s][lc + 0][lr] = rb0.x; Bs[s][lc + 1][lr] = rb0.y;
        Bs[s][lc + 2][lr] = rb0.z; Bs[s][lc + 3][lr] = rb0.w;
        Bs[s][lc + 4][lr] = rb1.x; Bs[s][lc + 5][lr] = rb1.y;
        Bs[s][lc + 6][lr] = rb1.z; Bs[s][lc + 7][lr] = rb1.w;
        __syncthreads();
        if (c + 1 < NC) {
            const int kn = (c + 1) << 4;
            ra0 = *(const float4*)(Ag + kn);
            ra1 = *(const float4*)(Ag + kn + 4);
            rb0 = *(const float4*)(Bg + kn);
            rb1 = *(const float4*)(Bg + kn + 4);
        }
#pragma unroll
        for (int kk = 0; kk < 16; kk++) {
            float ar[8], br[8];
            *(float4*)&ar[0] = *(const float4*)&As[s][kk][ty * 4];
            *(float4*)&ar[4] = *(const float4*)&As[s][kk][64 + ty * 4];
            *(float4*)&br[0] = *(const float4*)&Bs[s][kk][tx * 4];
            *(float4*)&br[4] = *(const float4*)&Bs[s][kk][64 + tx * 4];
#pragma unroll
            for (int i = 0; i < 8; i++)
#pragma unroll
                for (int j = 0; j < 8; j++)
                    acc[i][j] = fmaf(ar[i], br[j], acc[i][j]);
        }
    }

    float cs[8], cs2[8];
#pragma unroll
    for (int j8 = 0; j8 < 8; j8++) { cs[j8] = 0.f; cs2[j8] = 0.f; }

#pragma unroll
    for (int ih = 0; ih < 2; ih++) {
#pragma unroll
        for (int i = 0; i < 4; i++) {
            int r = m0 + ih * 64 + ty * 4 + i;
            float* Crow = C + (size_t)r * N + n0;
#pragma unroll
            for (int jh = 0; jh < 2; jh++) {
                int cb = jh * 64 + tx * 4;
                float4 v;
                v.x = acc[ih * 4 + i][jh * 4 + 0] + bias[n0 + cb + 0];
                v.y = acc[ih * 4 + i][jh * 4 + 1] + bias[n0 + cb + 1];
                v.z = acc[ih * 4 + i][jh * 4 + 2] + bias[n0 + cb + 2];
                v.w = acc[ih * 4 + i][jh * 4 + 3] + bias[n0 + cb + 3];
                *(float4*)(Crow + cb) = v;
                if (layer >= 0) {
                    cs[jh * 4 + 0] += v.x;  cs2[jh * 4 + 0] += v.x * v.x;
                    cs[jh * 4 + 1] += v.y;  cs2[jh * 4 + 1] += v.y * v.y;
                    cs[jh * 4 + 2] += v.z;  cs2[jh * 4 + 2] += v.z * v.z;
                    cs[jh * 4 + 3] += v.w;  cs2[jh * 4 + 3] += v.w * v.w;
                }
            }
        }
    }
    if (layer >= 0) {
        __syncthreads();
        float* sst = &As[0][0][0];
        if (tid < 256) sst[tid] = 0.f;
        __syncthreads();
#pragma unroll
        for (int jh = 0; jh < 2; jh++)
#pragma unroll
            for (int j = 0; j < 4; j++) {
                int cl = jh * 64 + tx * 4 + j;
                atomicAdd(&sst[cl], cs[jh * 4 + j]);
                atomicAdd(&sst[128 + cl], cs2[jh * 4 + j]);
            }
        __syncthreads();
        if (tid < 128) {
            float* gs = &g_stats[layer * 2 * HID];
            atomicAdd(&gs[n0 + tid], sst[tid]);
            atomicAdd(&gs[HID + n0 + tid], sst[128 + tid]);
        }
    }
}

// ---------------- 64x64 NT GEMM (R1-proven, output layer) ----------------
__global__ __launch_bounds__(256) void gemm64_nt(
    const float* __restrict__ A, const float* __restrict__ B,
    const float* __restrict__ bias, float* __restrict__ C,
    int M, int N, int K)
{
    __shared__ float As[8][68];
    __shared__ float Bs[8][68];
    const int tid = threadIdx.x;
    const int tx = tid & 15, ty = tid >> 4;
    const int m0 = blockIdx.y * 64, n0 = blockIdx.x * 64;
    float acc[4][4];
#pragma unroll
    for (int i = 0; i < 4; i++)
#pragma unroll
        for (int j = 0; j < 4; j++) acc[i][j] = 0.f;

    const int half = tid >> 7;
    const int lt = tid & 127;
    const int lr = lt >> 1;
    const int lcv = (lt & 1) << 2;
    const float* G = half ? (B + (size_t)(n0 + lr) * K + lcv)
                          : (A + (size_t)(m0 + lr) * K + lcv);

    for (int k0 = 0; k0 < K; k0 += 8) {
        float4 g4 = *(const float4*)(G + k0);
        if (half == 0) {
            As[lcv + 0][lr] = g4.x; As[lcv + 1][lr] = g4.y; As[lcv + 2][lr] = g4.z; As[lcv + 3][lr] = g4.w;
        } else {
            Bs[lcv + 0][lr] = g4.x; Bs[lcv + 1][lr] = g4.y; Bs[lcv + 2][lr] = g4.z; Bs[lcv + 3][lr] = g4.w;
        }
        __syncthreads();
#pragma unroll
        for (int kk = 0; kk < 8; kk++) {
            float ar[4], br[4];
            *(float4*)&ar[0] = *(const float4*)&As[kk][ty * 4];
            *(float4*)&br[0] = *(const float4*)&Bs[kk][tx * 4];
#pragma unroll
            for (int i = 0; i < 4; i++)
#pragma unroll
                for (int j = 0; j < 4; j++)
                    acc[i][j] = fmaf(ar[i], br[j], acc[i][j]);
        }
        __syncthreads();
    }
#pragma unroll
    for (int i = 0; i < 4; i++) {
        int r = m0 + ty * 4 + i;
        float4 v;
        v.x = acc[i][0] + bias[n0 + tx * 4 + 0];
        v.y = acc[i][1] + bias[n0 + tx * 4 + 1];
        v.z = acc[i][2] + bias[n0 + tx * 4 + 2];
        v.w = acc[i][3] + bias[n0 + tx * 4 + 3];
        *(float4*)(C + (size_t)r * N + n0 + tx * 4) = v;
    }
}

// ---------------- embed L2 norm + ||e||^2 (R1-proven) ----------------
__global__ __launch_bounds__(256) void embed_norm_kernel(const float* __restrict__ Eraw)
{
    int row = blockIdx.x * 8 + (threadIdx.x >> 5);
    int lane = threadIdx.x & 31;
    float v0 = Eraw[row * VQd + lane];
    float v1 = Eraw[row * VQd + 32 + lane];
    float s = v0 * v0 + v1 * v1;
#pragma unroll
    for (int off = 16; off; off >>= 1) s += __shfl_xor_sync(0xffffffffu, s, off);
    float norm = sqrtf(s);
    float sc = 1.f / (norm + EPS_N);
    g_embed[row * VQd + lane] = v0 * sc;
    g_embed[row * VQd + 32 + lane] = v1 * sc;
    if (lane == 0) g_enorm2[row] = s * sc * sc;
}

// ---------------- hidden projection + L2 normalize (R1-proven) ----------------
__global__ __launch_bounds__(256) void hproj_kernel(
    const float* __restrict__ Hin, const float* __restrict__ Pw,
    const float* __restrict__ Pb, float* __restrict__ Hout)
{
    __shared__ float Ash[32][132];
    __shared__ float Wsh[32][65];
    const int tid = threadIdx.x;
    const int b = blockIdx.y;
    const int t0 = blockIdx.x * 128;
    const int tx = tid & 15, ty = tid >> 4;
    float acc[8][4];
#pragma unroll
    for (int i = 0; i < 8; i++)
#pragma unroll
        for (int j = 0; j < 4; j++) acc[i][j] = 0.f;

    const int lt = tid & 127;
    const int ldr = tid >> 7;
    const int wv = tid >> 5;
    const int wd = tid & 31;

    for (int d0 = 0; d0 < Dd; d0 += 32) {
#pragma unroll
        for (int dd = ldr; dd < 32; dd += 2)
            Ash[dd][lt] = Hin[(size_t)(b * Dd + d0 + dd) * Tt + t0 + lt];
#pragma unroll
        for (int vv = wv; vv < 64; vv += 8)
            Wsh[wd][vv] = Pw[vv * Dd + d0 + wd];
        __syncthreads();
#pragma unroll
        for (int kk = 0; kk < 32; kk++) {
            float ar[8], br[4];
            *(float4*)&ar[0] = *(const float4*)&Ash[kk][ty * 4];
            *(float4*)&ar[4] = *(const float4*)&Ash[kk][64 + ty * 4];
#pragma unroll
            for (int j = 0; j < 4; j++) br[j] = Wsh[kk][tx * 4 + j];
#pragma unroll
            for (int i = 0; i < 8; i++)
#pragma unroll
                for (int j = 0; j < 4; j++)
                    acc[i][j] = fmaf(ar[i], br[j], acc[i][j]);
        }
        __syncthreads();
    }
    float bb[4];
#pragma unroll
    for (int j = 0; j < 4; j++) bb[j] = Pb[tx * 4 + j];
#pragma unroll
    for (int i = 0; i < 8; i++) {
        float hv[4]; float ssq = 0.f;
#pragma unroll
        for (int j = 0; j < 4; j++) { hv[j] = acc[i][j] + bb[j]; ssq += hv[j] * hv[j]; }
#pragma unroll
        for (int off = 8; off; off >>= 1) ssq += __shfl_xor_sync(0xffffffffu, ssq, off, 16);
        float sc = 1.f / (sqrtf(ssq) + EPS_N);
        int t = t0 + ((i < 4) ? ty * 4 + i : 64 + ty * 4 + (i - 4));
        float4 o = make_float4(hv[0] * sc, hv[1] * sc, hv[2] * sc, hv[3] * sc);
        *(float4*)&Hout[(size_t)(b * Tt + t) * VQd + tx * 4] = o;
    }
}

// ---------------- coarse tf32 score pass + candidate emission (R7-proven) ----------------
__global__ __launch_bounds__(256) void coarse_kernel()
{
    extern __shared__ float smc[];
    float* sA = smc;
    float* sB = smc + 128 * CPITCH;
    float* e2sm = smc + 2 * 128 * CPITCH;
    __shared__ unsigned smax[128];
    __shared__ int cnt[128];

    const int tid = threadIdx.x;
    const int lane = tid & 31, wid = tid >> 5;
    const int wm = wid >> 2, wn = wid & 3;
    const int g = lane >> 2, tig = lane & 3;
    const int m0 = blockIdx.x * 128;

    for (int i = tid; i < 2048; i += 256) {
        int r = i >> 4, q = i & 15;
        *(float4*)&sA[r * CPITCH + q * 4] = *(const float4*)&g_h[(size_t)(m0 + r) * VQd + q * 4];
    }
    if (tid < 128) { smax[tid] = 0u; cnt[tid] = 0; }
    __syncthreads();

    for (int ch = 0; ch < 32; ch++) {
        const int n0 = ch * 128;
        for (int i = tid; i < 2048; i += 256) {
            int r = i >> 4, q = i & 15;
            *(float4*)&sB[r * CPITCH + q * 4] = *(const float4*)&g_embed[(size_t)(n0 + r) * VQd + q * 4];
        }
        if (tid < 128) e2sm[tid] = g_enorm2[n0 + tid];
        __syncthreads();

        float acc[4][4][4];
#pragma unroll
        for (int mt = 0; mt < 4; mt++)
#pragma unroll
            for (int nt = 0; nt < 4; nt++)
#pragma unroll
                for (int q = 0; q < 4; q++) acc[mt][nt][q] = 0.f;

#pragma unroll
        for (int ks = 0; ks < 8; ks++) {
            const int kb = ks * 8;
            uint32_t a[4][4];
#pragma unroll
            for (int mt = 0; mt < 4; mt++) {
                const uint32_t* pa = (const uint32_t*)&sA[(wm * 64 + mt * 16 + g) * CPITCH + kb + tig];
                a[mt][0] = pa[0];
                a[mt][1] = pa[8 * CPITCH];
                a[mt][2] = pa[4];
                a[mt][3] = pa[8 * CPITCH + 4];
            }
            uint32_t b[4][2];
#pragma unroll
            for (int nt = 0; nt < 4; nt++) {
                const uint32_t* pb = (const uint32_t*)&sB[(wn * 32 + nt * 8 + g) * CPITCH + kb + tig];
                b[nt][0] = pb[0];
                b[nt][1] = pb[4];
            }
#pragma unroll
            for (int mt = 0; mt < 4; mt++)
#pragma unroll
                for (int nt = 0; nt < 4; nt++)
                    mma_tf32(acc[mt][nt], a[mt], b[nt]);
        }

        float rmax[4][2];
#pragma unroll
        for (int mt = 0; mt < 4; mt++) {
            rmax[mt][0] = -3.4e38f; rmax[mt][1] = -3.4e38f;
#pragma unroll
            for (int nt = 0; nt < 4; nt++) {
                int col0 = wn * 32 + nt * 8 + 2 * tig;
                float e20 = e2sm[col0], e21 = e2sm[col0 + 1];
                float s0 = 2.f * acc[mt][nt][0] - e20;
                float s1 = 2.f * acc[mt][nt][1] - e21;
                float s2 = 2.f * acc[mt][nt][2] - e20;
                float s3 = 2.f * acc[mt][nt][3] - e21;
                rmax[mt][0] = fmaxf(rmax[mt][0], fmaxf(s0, s1));
                rmax[mt][1] = fmaxf(rmax[mt][1], fmaxf(s2, s3));
            }
        }
#pragma unroll
        for (int off = 1; off <= 2; off <<= 1)
#pragma unroll
            for (int mt = 0; mt < 4; mt++)
#pragma unroll
                for (int h = 0; h < 2; h++)
                    rmax[mt][h] = fmaxf(rmax[mt][h], __shfl_xor_sync(0xffffffffu, rmax[mt][h], off));
        if (tig == 0) {
#pragma unroll
            for (int mt = 0; mt < 4; mt++) {
                atomicMax(&smax[wm * 64 + mt * 16 + g], fmap(rmax[mt][0]));
                atomicMax(&smax[wm * 64 + mt * 16 + g + 8], fmap(rmax[mt][1]));
            }
        }
        __syncthreads();

#pragma unroll
        for (int mt = 0; mt < 4; mt++) {
            int rr0 = wm * 64 + mt * 16 + g;
            float th0 = funmap(smax[rr0]) - CTH;
            float th1 = funmap(smax[rr0 + 8]) - CTH;
#pragma unroll
            for (int nt = 0; nt < 4; nt++) {
                int col0 = wn * 32 + nt * 8 + 2 * tig;
                float e20 = e2sm[col0], e21 = e2sm[col0 + 1];
                float s0 = 2.f * acc[mt][nt][0] - e20;
                float s1 = 2.f * acc[mt][nt][1] - e21;
                float s2 = 2.f * acc[mt][nt][2] - e20;
                float s3 = 2.f * acc[mt][nt][3] - e21;
                if (s0 >= th0) { int p = atomicAdd(&cnt[rr0], 1); if (p < CCAP) g_cand[(size_t)(m0 + rr0) * CCAP + p] = n0 + col0; }
                if (s1 >= th0) { int p = atomicAdd(&cnt[rr0], 1); if (p < CCAP) g_cand[(size_t)(m0 + rr0) * CCAP + p] = n0 + col0 + 1; }
                if (s2 >= th1) { int p = atomicAdd(&cnt[rr0 + 8], 1); if (p < CCAP) g_cand[(size_t)(m0 + rr0 + 8) * CCAP + p] = n0 + col0; }
                if (s3 >= th1) { int p = atomicAdd(&cnt[rr0 + 8], 1); if (p < CCAP) g_cand[(size_t)(m0 + rr0 + 8) * CCAP + p] = n0 + col0 + 1; }
            }
        }
        __syncthreads();
    }
    if (tid < 128) g_ccnt[m0 + tid] = cnt[tid];
}

// ---------------- exact rescore (R7-proven, bit-identical to R1 score arithmetic) ----------------
__global__ __launch_bounds__(256) void rescore_kernel()
{
    __shared__ float sh[8][VQd];
    const int tid = threadIdx.x;
    const int lane = tid & 31, wid = tid >> 5;
    const int token = blockIdx.x * 8 + wid;

    sh[wid][lane] = g_h[(size_t)token * VQd + lane];
    sh[wid][lane + 32] = g_h[(size_t)token * VQd + lane + 32];
    __syncwarp();

    int cnt = g_ccnt[token];
    unsigned long long best = 0ull;

    if (cnt > 0 && cnt <= CCAP) {
        for (int ci = lane; ci < cnt; ci += 32) {
            int code = g_cand[(size_t)token * CCAP + ci];
            float acc = 0.f;
            const float* e = &g_embed[(size_t)code * VQd];
#pragma unroll
            for (int q = 0; q < 16; q++) {
                float4 ev = *(const float4*)&e[q * 4];
                acc = fmaf(sh[wid][q * 4 + 0], ev.x, acc);
                acc = fmaf(sh[wid][q * 4 + 1], ev.y, acc);
                acc = fmaf(sh[wid][q * 4 + 2], ev.z, acc);
                acc = fmaf(sh[wid][q * 4 + 3], ev.w, acc);
            }
            float s = 2.f * acc - g_enorm2[code];
            unsigned u = __float_as_uint(s);
            u = (u & 0x80000000u) ? ~u : (u | 0x80000000u);
            unsigned long long key =
                ((unsigned long long)u << 32) | (unsigned)(0xFFFFFFFFu - (unsigned)code);
            best = (key > best) ? key : best;
        }
    } else {
        for (int code = lane; code < K_CB; code += 32) {
            float acc = 0.f;
            const float* e = &g_embed[(size_t)code * VQd];
#pragma unroll
            for (int q = 0; q < 16; q++) {
                float4 ev = *(const float4*)&e[q * 4];
                acc = fmaf(sh[wid][q * 4 + 0], ev.x, acc);
                acc = fmaf(sh[wid][q * 4 + 1], ev.y, acc);
                acc = fmaf(sh[wid][q * 4 + 2], ev.z, acc);
                acc = fmaf(sh[wid][q * 4 + 3], ev.w, acc);
            }
            float s = 2.f * acc - g_enorm2[code];
            unsigned u = __float_as_uint(s);
            u = (u & 0x80000000u) ? ~u : (u | 0x80000000u);
            unsigned long long key =
                ((unsigned long long)u << 32) | (unsigned)(0xFFFFFFFFu - (unsigned)code);
            best = (key > best) ? key : best;
        }
    }
#pragma unroll
    for (int off = 16; off; off >>= 1) {
        unsigned long long o = __shfl_xor_sync(0xffffffffu, best, off);
        best = (o > best) ? o : best;
    }
    if (lane == 0) g_best[token] = best;
}

// ---------------- gather masked codebook rows + emit codes (R1-proven) ----------------
__global__ __launch_bounds__(256) void gather_kernel(
    const int* __restrict__ attn, float* __restrict__ out_codes, int write_codes)
{
    int idx = blockIdx.x * 256 + threadIdx.x;
    int bt = idx >> 4;
    int v = (idx & 15) << 2;
    unsigned long long key = g_best[bt];
    int code = (int)(0xFFFFFFFFu - (unsigned)(key & 0xFFFFFFFFull));
    int msk = (attn[bt] == 1);
    float4 e = msk ? *(const float4*)&g_embed[(size_t)code * VQd + v]
                   : make_float4(0.f, 0.f, 0.f, 0.f);
    *(float4*)&g_esel[(size_t)bt * VQd + v] = e;
    if (write_codes && (idx & 15) == 0)
        out_codes[bt] = msk ? (float)code : 0.f;
}

// ---------------- host launcher ----------------
extern "C" void kernel_launch(void* const* d_in, const int* in_sizes, int n_in,
                              void* d_out, int out_size)
{
    const float* h_in     = (const float*)d_in[0];
    const int*   attn     = (const int*)  d_in[1];
    const float* proj_w   = (const float*)d_in[2];
    const float* proj_b   = (const float*)d_in[3];
    const float* inv_w    = (const float*)d_in[4];
    const float* inv_b    = (const float*)d_in[5];
    const float* mlp_w_in = (const float*)d_in[6];
    const float* mlp_b_in = (const float*)d_in[7];
    const float* w_mid    = (const float*)d_in[8];
    const float* b_mid    = (const float*)d_in[9];
    const float* w_out    = (const float*)d_in[10];
    const float* b_out    = (const float*)d_in[11];
    const float* gamma    = (const float*)d_in[12];
    const float* beta     = (const float*)d_in[13];
    float* out = (float*)d_out;

    void *px_, *py_, *pes_, *ph_;
    cudaGetSymbolAddress(&px_, g_x);
    cudaGetSymbolAddress(&py_, g_y);
    cudaGetSymbolAddress(&pes_, g_esel);
    cudaGetSymbolAddress(&ph_, g_h);
    float* px = (float*)px_;
    float* py = (float*)py_;
    float* pes = (float*)pes_;
    float* ph = (float*)ph_;

    const int COARSE_SMEM = (2 * 128 * CPITCH + 128) * 4;
    cudaFuncSetAttribute(coarse_kernel,
                         cudaFuncAttributeMaxDynamicSharedMemorySize, COARSE_SMEM);

    // 0) zero all per-layer BN stats once
    zero_all_stats_kernel<<<(N_MID * 2 * HID + 255) / 256, 256>>>();

    // 1) codebook MLP (fp32, chains bit-identical; stats fused into GEMM epilogue)
    layer0_kernel<<<dim3(4, 256), 256>>>(mlp_w_in, mlp_b_in, gamma, beta, px);
    for (int i = 0; i < N_MID; i++) {
        gemm128_nt<<<dim3(HID / 128, K_CB / 128), 256>>>(
            px, w_mid + (size_t)i * HID * HID, b_mid + i * HID, py, K_CB, HID, HID, i);
        bn_norm_relu_kernel<<<(K_CB * HID / 4) / 1024, 256>>>(
            py, gamma + (i + 1) * HID, beta + (i + 1) * HID, px, i);
    }
    gemm64_nt<<<dim3(1, K_CB / 64), 256>>>(px, w_out, b_out, py, K_CB, VQd, HID);
    embed_norm_kernel<<<K_CB / 8, 256>>>(py);

    // 2) hidden projection + L2 normalize
    hproj_kernel<<<dim3(Tt / 128, Bb), 256>>>(h_in, proj_w, proj_b, ph);

    // 3) certified two-pass argmax: tf32 coarse + exact fp32 rescore
    coarse_kernel<<<NTOK / 128, 256, COARSE_SMEM>>>();
    rescore_kernel<<<NTOK / 8, 256>>>();

    // 4) masked gather + codes
    int write_codes = (out_size >= NTOK * Dd + NTOK) ? 1 : 0;
    gather_kernel<<<NTOK * 16 / 256, 256>>>(attn, out + (size_t)NTOK * Dd, write_codes);

    // 5) inverse projection straight into d_out (no stats)
    gemm128_nt<<<dim3(Dd / 128, NTOK / 128), 256>>>(
        pes, inv_w, inv_b, out, NTOK, Dd, VQd, -1);
}

// round 15
// speedup vs baseline: 1.6416x; 1.0319x over previous
#include <cuda_runtime.h>
#include <cuda_bf16.h>
#include <stdint.h>

// Problem constants
#define K_CB   4096
#define HID    1024
#define VQd    64
#define Dd     768
#define Bb     8
#define Tt     2048
#define NTOK   (Bb*Tt)
#define L2b    12
#define N_MID  4
#define EPS_N  1e-6f
#define EPS_BN 1e-5f

#define CCAP   256
#define CTH    0.03f
#define CPITCH 68

// ---------------- scratch (device globals) ----------------
__device__ float g_x[K_CB * HID];
__device__ float g_y[K_CB * HID];
__device__ float g_embed[K_CB * VQd];
__device__ float g_enorm2[K_CB];
__device__ float g_h[NTOK * VQd];
__device__ float g_esel[NTOK * VQd];
__device__ float g_stats[N_MID * 2 * HID];
__device__ int g_ccnt[NTOK];
__device__ int g_cand[(size_t)NTOK * CCAP];

// ---------------- helpers ----------------
static __device__ __forceinline__ void mma_tf32(float* c, const uint32_t* a,
                                                const uint32_t* b) {
    asm volatile(
        "mma.sync.aligned.m16n8k8.row.col.f32.tf32.tf32.f32 "
        "{%0,%1,%2,%3}, {%4,%5,%6,%7}, {%8,%9}, {%0,%1,%2,%3};"
        : "+f"(c[0]), "+f"(c[1]), "+f"(c[2]), "+f"(c[3])
        : "r"(a[0]), "r"(a[1]), "r"(a[2]), "r"(a[3]), "r"(b[0]), "r"(b[1]));
}
static __device__ __forceinline__ unsigned fmap(float s) {
    unsigned u = __float_as_uint(s);
    return (u & 0x80000000u) ? ~u : (u | 0x80000000u);
}
static __device__ __forceinline__ float funmap(unsigned v) {
    unsigned u = (v & 0x80000000u) ? (v ^ 0x80000000u) : ~v;
    return __uint_as_float(u);
}

// ---------------- small utility kernels ----------------
__global__ void zero_all_stats_kernel() {
    int i = blockIdx.x * 256 + threadIdx.x;
    if (i < N_MID * 2 * HID) g_stats[i] = 0.f;
}

// ---------------- layer 0 (R1-proven) ----------------
__global__ __launch_bounds__(256) void layer0_kernel(
    const float* __restrict__ W, const float* __restrict__ bias,
    const float* __restrict__ gamma, const float* __restrict__ beta,
    float* __restrict__ X)
{
    int f = blockIdx.x * 256 + threadIdx.x;
    int k0 = blockIdx.y * 16;
    float w[L2b];
    float sw = 0.f, sw2 = 0.f;
#pragma unroll
    for (int j = 0; j < L2b; j++) {
        w[j] = W[f * L2b + j];
        sw += w[j]; sw2 += w[j] * w[j];
    }
    float b = bias[f];
    float m = b + 0.5f * sw;
    float v = 0.25f * sw2;
    float rstd = rsqrtf(v + EPS_BN);
    float ga = gamma[f] * rstd;
    float be = beta[f];
#pragma unroll 4
    for (int kk = 0; kk < 16; kk++) {
        int k = k0 + kk;
        float y = b;
#pragma unroll
        for (int j = 0; j < L2b; j++)
            if ((k >> (11 - j)) & 1) y += w[j];
        float o = (y - m) * ga + be;
        X[k * HID + f] = fmaxf(o, 0.f);
    }
}

// ---------------- BN normalize + ReLU (R9-proven) ----------------
__global__ __launch_bounds__(256) void bn_norm_relu_kernel(
    const float* __restrict__ Y, const float* __restrict__ gamma,
    const float* __restrict__ beta, float* __restrict__ X, int layer)
{
    const float* st = &g_stats[layer * 2 * HID];
    int base = blockIdx.x * 1024 + threadIdx.x;
#pragma unroll
    for (int u = 0; u < 4; u++) {
        int i4 = base + u * 256;
        int f0 = (i4 * 4) & (HID - 1);
        float4 y = ((const float4*)Y)[i4];
        float yv[4] = { y.x, y.y, y.z, y.w };
        float out[4];
#pragma unroll
        for (int j = 0; j < 4; j++) {
            int f = f0 + j;
            float m = st[f] * (1.f / K_CB);
            float var = st[HID + f] * (1.f / K_CB) - m * m;
            float o = (yv[j] - m) * rsqrtf(var + EPS_BN) * gamma[f] + beta[f];
            out[j] = fmaxf(o, 0.f);
        }
        ((float4*)X)[i4] = make_float4(out[0], out[1], out[2], out[3]);
    }
}

// ---------------- fp32 NT GEMM, double-buffered BK=16 + fused BN stats (R9-proven) ----------------
__global__ __launch_bounds__(256, 2) void gemm128_nt(
    const float* __restrict__ A, const float* __restrict__ B,
    const float* __restrict__ bias, float* __restrict__ C,
    int M, int N, int K, int layer)
{
    __shared__ float As[2][16][132];
    __shared__ float Bs[2][16][132];
    const int tid = threadIdx.x;
    const int tx = tid & 15, ty = tid >> 4;
    const int m0 = blockIdx.y * 128, n0 = blockIdx.x * 128;
    const int lr = tid >> 1;
    const int lc = (tid & 1) << 3;
    const float* Ag = A + (size_t)(m0 + lr) * K + lc;
    const float* Bg = B + (size_t)(n0 + lr) * K + lc;

    float acc[8][8];
#pragma unroll
    for (int i = 0; i < 8; i++)
#pragma unroll
        for (int j = 0; j < 8; j++) acc[i][j] = 0.f;

    float4 ra0 = *(const float4*)(Ag);
    float4 ra1 = *(const float4*)(Ag + 4);
    float4 rb0 = *(const float4*)(Bg);
    float4 rb1 = *(const float4*)(Bg + 4);

    const int NC = K >> 4;
    for (int c = 0; c < NC; c++) {
        const int s = c & 1;
        As[s][lc + 0][lr] = ra0.x; As[s][lc + 1][lr] = ra0.y;
        As[s][lc + 2][lr] = ra0.z; As[s][lc + 3][lr] = ra0.w;
        As[s][lc + 4][lr] = ra1.x; As[s][lc + 5][lr] = ra1.y;
        As[s][lc + 6][lr] = ra1.z; As[s][lc + 7][lr] = ra1.w;
        Bs[s][lc + 0][lr] = rb0.x; Bs[s][lc + 1][lr] = rb0.y;
        Bs[s][lc + 2][lr] = rb0.z; Bs[s][lc + 3][lr] = rb0.w;
        Bs[s][lc + 4][lr] = rb1.x; Bs[s][lc + 5][lr] = rb1.y;
        Bs[s][lc + 6][lr] = rb1.z; Bs[s][lc + 7][lr] = rb1.w;
        __syncthreads();
        if (c + 1 < NC) {
            const int kn = (c + 1) << 4;
            ra0 = *(const float4*)(Ag + kn);
            ra1 = *(const float4*)(Ag + kn + 4);
            rb0 = *(const float4*)(Bg + kn);
            rb1 = *(const float4*)(Bg + kn + 4);
        }
#pragma unroll
        for (int kk = 0; kk < 16; kk++) {
            float ar[8], br[8];
            *(float4*)&ar[0] = *(const float4*)&As[s][kk][ty * 4];
            *(float4*)&ar[4] = *(const float4*)&As[s][kk][64 + ty * 4];
            *(float4*)&br[0] = *(const float4*)&Bs[s][kk][tx * 4];
            *(float4*)&br[4] = *(const float4*)&Bs[s][kk][64 + tx * 4];
#pragma unroll
            for (int i = 0; i < 8; i++)
#pragma unroll
                for (int j = 0; j < 8; j++)
                    acc[i][j] = fmaf(ar[i], br[j], acc[i][j]);
        }
    }

    float cs[8], cs2[8];
#pragma unroll
    for (int j8 = 0; j8 < 8; j8++) { cs[j8] = 0.f; cs2[j8] = 0.f; }

#pragma unroll
    for (int ih = 0; ih < 2; ih++) {
#pragma unroll
        for (int i = 0; i < 4; i++) {
            int r = m0 + ih * 64 + ty * 4 + i;
            float* Crow = C + (size_t)r * N + n0;
#pragma unroll
            for (int jh = 0; jh < 2; jh++) {
                int cb = jh * 64 + tx * 4;
                float4 v;
                v.x = acc[ih * 4 + i][jh * 4 + 0] + bias[n0 + cb + 0];
                v.y = acc[ih * 4 + i][jh * 4 + 1] + bias[n0 + cb + 1];
                v.z = acc[ih * 4 + i][jh * 4 + 2] + bias[n0 + cb + 2];
                v.w = acc[ih * 4 + i][jh * 4 + 3] + bias[n0 + cb + 3];
                *(float4*)(Crow + cb) = v;
                if (layer >= 0) {
                    cs[jh * 4 + 0] += v.x;  cs2[jh * 4 + 0] += v.x * v.x;
                    cs[jh * 4 + 1] += v.y;  cs2[jh * 4 + 1] += v.y * v.y;
                    cs[jh * 4 + 2] += v.z;  cs2[jh * 4 + 2] += v.z * v.z;
                    cs[jh * 4 + 3] += v.w;  cs2[jh * 4 + 3] += v.w * v.w;
                }
            }
        }
    }
    if (layer >= 0) {
        __syncthreads();
        float* sst = &As[0][0][0];
        if (tid < 256) sst[tid] = 0.f;
        __syncthreads();
#pragma unroll
        for (int jh = 0; jh < 2; jh++)
#pragma unroll
            for (int j = 0; j < 4; j++) {
                int cl = jh * 64 + tx * 4 + j;
                atomicAdd(&sst[cl], cs[jh * 4 + j]);
                atomicAdd(&sst[128 + cl], cs2[jh * 4 + j]);
            }
        __syncthreads();
        if (tid < 128) {
            float* gs = &g_stats[layer * 2 * HID];
            atomicAdd(&gs[n0 + tid], sst[tid]);
            atomicAdd(&gs[HID + n0 + tid], sst[128 + tid]);
        }
    }
}

// ---------------- 64x64 NT GEMM, double-buffered BK=16 ----------------
// Per-output fmaf chain bit-identical to R1 gemm64 (k ascending, same fragment indices).
__global__ __launch_bounds__(256) void gemm64_nt(
    const float* __restrict__ A, const float* __restrict__ B,
    const float* __restrict__ bias, float* __restrict__ C,
    int M, int N, int K)
{
    __shared__ float As[2][16][68];
    __shared__ float Bs[2][16][68];
    const int tid = threadIdx.x;
    const int tx = tid & 15, ty = tid >> 4;
    const int m0 = blockIdx.y * 64, n0 = blockIdx.x * 64;
    float acc[4][4];
#pragma unroll
    for (int i = 0; i < 4; i++)
#pragma unroll
        for (int j = 0; j < 4; j++) acc[i][j] = 0.f;

    const int half = tid >> 7;
    const int lt = tid & 127;
    const int lr = lt >> 1;                 // 0..63
    const int lcv = (lt & 1) << 3;          // 0 or 8
    const float* G = half ? (B + (size_t)(n0 + lr) * K + lcv)
                          : (A + (size_t)(m0 + lr) * K + lcv);

    float4 r0 = *(const float4*)(G);
    float4 r1 = *(const float4*)(G + 4);

    const int NC = K >> 4;
    for (int c = 0; c < NC; c++) {
        const int s = c & 1;
        float (*S)[68] = half ? Bs[s] : As[s];
        S[lcv + 0][lr] = r0.x; S[lcv + 1][lr] = r0.y;
        S[lcv + 2][lr] = r0.z; S[lcv + 3][lr] = r0.w;
        S[lcv + 4][lr] = r1.x; S[lcv + 5][lr] = r1.y;
        S[lcv + 6][lr] = r1.z; S[lcv + 7][lr] = r1.w;
        __syncthreads();
        if (c + 1 < NC) {
            const int kn = (c + 1) << 4;
            r0 = *(const float4*)(G + kn);
            r1 = *(const float4*)(G + kn + 4);
        }
#pragma unroll
        for (int kk = 0; kk < 16; kk++) {
            float ar[4], br[4];
            *(float4*)&ar[0] = *(const float4*)&As[s][kk][ty * 4];
            *(float4*)&br[0] = *(const float4*)&Bs[s][kk][tx * 4];
#pragma unroll
            for (int i = 0; i < 4; i++)
#pragma unroll
                for (int j = 0; j < 4; j++)
                    acc[i][j] = fmaf(ar[i], br[j], acc[i][j]);
        }
    }
#pragma unroll
    for (int i = 0; i < 4; i++) {
        int r = m0 + ty * 4 + i;
        float4 v;
        v.x = acc[i][0] + bias[n0 + tx * 4 + 0];
        v.y = acc[i][1] + bias[n0 + tx * 4 + 1];
        v.z = acc[i][2] + bias[n0 + tx * 4 + 2];
        v.w = acc[i][3] + bias[n0 + tx * 4 + 3];
        *(float4*)(C + (size_t)r * N + n0 + tx * 4) = v;
    }
}

// ---------------- embed L2 norm + ||e||^2 (R1-proven) ----------------
__global__ __launch_bounds__(256) void embed_norm_kernel(const float* __restrict__ Eraw)
{
    int row = blockIdx.x * 8 + (threadIdx.x >> 5);
    int lane = threadIdx.x & 31;
    float v0 = Eraw[row * VQd + lane];
    float v1 = Eraw[row * VQd + 32 + lane];
    float s = v0 * v0 + v1 * v1;
#pragma unroll
    for (int off = 16; off; off >>= 1) s += __shfl_xor_sync(0xffffffffu, s, off);
    float norm = sqrtf(s);
    float sc = 1.f / (norm + EPS_N);
    g_embed[row * VQd + lane] = v0 * sc;
    g_embed[row * VQd + 32 + lane] = v1 * sc;
    if (lane == 0) g_enorm2[row] = s * sc * sc;
}

// ---------------- hidden projection + L2 normalize (R1-proven) ----------------
__global__ __launch_bounds__(256) void hproj_kernel(
    const float* __restrict__ Hin, const float* __restrict__ Pw,
    const float* __restrict__ Pb, float* __restrict__ Hout)
{
    __shared__ float Ash[32][132];
    __shared__ float Wsh[32][65];
    const int tid = threadIdx.x;
    const int b = blockIdx.y;
    const int t0 = blockIdx.x * 128;
    const int tx = tid & 15, ty = tid >> 4;
    float acc[8][4];
#pragma unroll
    for (int i = 0; i < 8; i++)
#pragma unroll
        for (int j = 0; j < 4; j++) acc[i][j] = 0.f;

    const int lt = tid & 127;
    const int ldr = tid >> 7;
    const int wv = tid >> 5;
    const int wd = tid & 31;

    for (int d0 = 0; d0 < Dd; d0 += 32) {
#pragma unroll
        for (int dd = ldr; dd < 32; dd += 2)
            Ash[dd][lt] = Hin[(size_t)(b * Dd + d0 + dd) * Tt + t0 + lt];
#pragma unroll
        for (int vv = wv; vv < 64; vv += 8)
            Wsh[wd][vv] = Pw[vv * Dd + d0 + wd];
        __syncthreads();
#pragma unroll
        for (int kk = 0; kk < 32; kk++) {
            float ar[8], br[4];
            *(float4*)&ar[0] = *(const float4*)&Ash[kk][ty * 4];
            *(float4*)&ar[4] = *(const float4*)&Ash[kk][64 + ty * 4];
#pragma unroll
            for (int j = 0; j < 4; j++) br[j] = Wsh[kk][tx * 4 + j];
#pragma unroll
            for (int i = 0; i < 8; i++)
#pragma unroll
                for (int j = 0; j < 4; j++)
                    acc[i][j] = fmaf(ar[i], br[j], acc[i][j]);
        }
        __syncthreads();
    }
    float bb[4];
#pragma unroll
    for (int j = 0; j < 4; j++) bb[j] = Pb[tx * 4 + j];
#pragma unroll
    for (int i = 0; i < 8; i++) {
        float hv[4]; float ssq = 0.f;
#pragma unroll
        for (int j = 0; j < 4; j++) { hv[j] = acc[i][j] + bb[j]; ssq += hv[j] * hv[j]; }
#pragma unroll
        for (int off = 8; off; off >>= 1) ssq += __shfl_xor_sync(0xffffffffu, ssq, off, 16);
        float sc = 1.f / (sqrtf(ssq) + EPS_N);
        int t = t0 + ((i < 4) ? ty * 4 + i : 64 + ty * 4 + (i - 4));
        float4 o = make_float4(hv[0] * sc, hv[1] * sc, hv[2] * sc, hv[3] * sc);
        *(float4*)&Hout[(size_t)(b * Tt + t) * VQd + tx * 4] = o;
    }
}

// ---------------- coarse tf32 score pass + candidate emission (R7-proven) ----------------
__global__ __launch_bounds__(256) void coarse_kernel()
{
    extern __shared__ float smc[];
    float* sA = smc;
    float* sB = smc + 128 * CPITCH;
    float* e2sm = smc + 2 * 128 * CPITCH;
    __shared__ unsigned smax[128];
    __shared__ int cnt[128];

    const int tid = threadIdx.x;
    const int lane = tid & 31, wid = tid >> 5;
    const int wm = wid >> 2, wn = wid & 3;
    const int g = lane >> 2, tig = lane & 3;
    const int m0 = blockIdx.x * 128;

    for (int i = tid; i < 2048; i += 256) {
        int r = i >> 4, q = i & 15;
        *(float4*)&sA[r * CPITCH + q * 4] = *(const float4*)&g_h[(size_t)(m0 + r) * VQd + q * 4];
    }
    if (tid < 128) { smax[tid] = 0u; cnt[tid] = 0; }
    __syncthreads();

    for (int ch = 0; ch < 32; ch++) {
        const int n0 = ch * 128;
        for (int i = tid; i < 2048; i += 256) {
            int r = i >> 4, q = i & 15;
            *(float4*)&sB[r * CPITCH + q * 4] = *(const float4*)&g_embed[(size_t)(n0 + r) * VQd + q * 4];
        }
        if (tid < 128) e2sm[tid] = g_enorm2[n0 + tid];
        __syncthreads();

        float acc[4][4][4];
#pragma unroll
        for (int mt = 0; mt < 4; mt++)
#pragma unroll
            for (int nt = 0; nt < 4; nt++)
#pragma unroll
                for (int q = 0; q < 4; q++) acc[mt][nt][q] = 0.f;

#pragma unroll
        for (int ks = 0; ks < 8; ks++) {
            const int kb = ks * 8;
            uint32_t a[4][4];
#pragma unroll
            for (int mt = 0; mt < 4; mt++) {
                const uint32_t* pa = (const uint32_t*)&sA[(wm * 64 + mt * 16 + g) * CPITCH + kb + tig];
                a[mt][0] = pa[0];
                a[mt][1] = pa[8 * CPITCH];
                a[mt][2] = pa[4];
                a[mt][3] = pa[8 * CPITCH + 4];
            }
            uint32_t b[4][2];
#pragma unroll
            for (int nt = 0; nt < 4; nt++) {
                const uint32_t* pb = (const uint32_t*)&sB[(wn * 32 + nt * 8 + g) * CPITCH + kb + tig];
                b[nt][0] = pb[0];
                b[nt][1] = pb[4];
            }
#pragma unroll
            for (int mt = 0; mt < 4; mt++)
#pragma unroll
                for (int nt = 0; nt < 4; nt++)
                    mma_tf32(acc[mt][nt], a[mt], b[nt]);
        }

        float rmax[4][2];
#pragma unroll
        for (int mt = 0; mt < 4; mt++) {
            rmax[mt][0] = -3.4e38f; rmax[mt][1] = -3.4e38f;
#pragma unroll
            for (int nt = 0; nt < 4; nt++) {
                int col0 = wn * 32 + nt * 8 + 2 * tig;
                float e20 = e2sm[col0], e21 = e2sm[col0 + 1];
                float s0 = 2.f * acc[mt][nt][0] - e20;
                float s1 = 2.f * acc[mt][nt][1] - e21;
                float s2 = 2.f * acc[mt][nt][2] - e20;
                float s3 = 2.f * acc[mt][nt][3] - e21;
                rmax[mt][0] = fmaxf(rmax[mt][0], fmaxf(s0, s1));
                rmax[mt][1] = fmaxf(rmax[mt][1], fmaxf(s2, s3));
            }
        }
#pragma unroll
        for (int off = 1; off <= 2; off <<= 1)
#pragma unroll
            for (int mt = 0; mt < 4; mt++)
#pragma unroll
                for (int h = 0; h < 2; h++)
                    rmax[mt][h] = fmaxf(rmax[mt][h], __shfl_xor_sync(0xffffffffu, rmax[mt][h], off));
        if (tig == 0) {
#pragma unroll
            for (int mt = 0; mt < 4; mt++) {
                atomicMax(&smax[wm * 64 + mt * 16 + g], fmap(rmax[mt][0]));
                atomicMax(&smax[wm * 64 + mt * 16 + g + 8], fmap(rmax[mt][1]));
            }
        }
        __syncthreads();

#pragma unroll
        for (int mt = 0; mt < 4; mt++) {
            int rr0 = wm * 64 + mt * 16 + g;
            float th0 = funmap(smax[rr0]) - CTH;
            float th1 = funmap(smax[rr0 + 8]) - CTH;
#pragma unroll
            for (int nt = 0; nt < 4; nt++) {
                int col0 = wn * 32 + nt * 8 + 2 * tig;
                float e20 = e2sm[col0], e21 = e2sm[col0 + 1];
                float s0 = 2.f * acc[mt][nt][0] - e20;
                float s1 = 2.f * acc[mt][nt][1] - e21;
                float s2 = 2.f * acc[mt][nt][2] - e20;
                float s3 = 2.f * acc[mt][nt][3] - e21;
                if (s0 >= th0) { int p = atomicAdd(&cnt[rr0], 1); if (p < CCAP) g_cand[(size_t)(m0 + rr0) * CCAP + p] = n0 + col0; }
                if (s1 >= th0) { int p = atomicAdd(&cnt[rr0], 1); if (p < CCAP) g_cand[(size_t)(m0 + rr0) * CCAP + p] = n0 + col0 + 1; }
                if (s2 >= th1) { int p = atomicAdd(&cnt[rr0 + 8], 1); if (p < CCAP) g_cand[(size_t)(m0 + rr0 + 8) * CCAP + p] = n0 + col0; }
                if (s3 >= th1) { int p = atomicAdd(&cnt[rr0 + 8], 1); if (p < CCAP) g_cand[(size_t)(m0 + rr0 + 8) * CCAP + p] = n0 + col0 + 1; }
            }
        }
        __syncthreads();
    }
    if (tid < 128) g_ccnt[m0 + tid] = cnt[tid];
}

// ---------------- exact rescore + fused gather (scores bit-identical to R1) ----------------
__global__ __launch_bounds__(256) void rescore_gather_kernel(
    const int* __restrict__ attn, float* __restrict__ out_codes, int write_codes)
{
    __shared__ float sh[8][VQd];
    const int tid = threadIdx.x;
    const int lane = tid & 31, wid = tid >> 5;
    const int token = blockIdx.x * 8 + wid;

    sh[wid][lane] = g_h[(size_t)token * VQd + lane];
    sh[wid][lane + 32] = g_h[(size_t)token * VQd + lane + 32];
    __syncwarp();

    int cnt = g_ccnt[token];
    unsigned long long best = 0ull;

    if (cnt > 0 && cnt <= CCAP) {
        for (int ci = lane; ci < cnt; ci += 32) {
            int code = g_cand[(size_t)token * CCAP + ci];
            float acc = 0.f;
            const float* e = &g_embed[(size_t)code * VQd];
#pragma unroll
            for (int q = 0; q < 16; q++) {
                float4 ev = *(const float4*)&e[q * 4];
                acc = fmaf(sh[wid][q * 4 + 0], ev.x, acc);
                acc = fmaf(sh[wid][q * 4 + 1], ev.y, acc);
                acc = fmaf(sh[wid][q * 4 + 2], ev.z, acc);
                acc = fmaf(sh[wid][q * 4 + 3], ev.w, acc);
            }
            float s = 2.f * acc - g_enorm2[code];
            unsigned u = __float_as_uint(s);
            u = (u & 0x80000000u) ? ~u : (u | 0x80000000u);
            unsigned long long key =
                ((unsigned long long)u << 32) | (unsigned)(0xFFFFFFFFu - (unsigned)code);
            best = (key > best) ? key : best;
        }
    } else {
        for (int code = lane; code < K_CB; code += 32) {
            float acc = 0.f;
            const float* e = &g_embed[(size_t)code * VQd];
#pragma unroll
            for (int q = 0; q < 16; q++) {
                float4 ev = *(const float4*)&e[q * 4];
                acc = fmaf(sh[wid][q * 4 + 0], ev.x, acc);
                acc = fmaf(sh[wid][q * 4 + 1], ev.y, acc);
                acc = fmaf(sh[wid][q * 4 + 2], ev.z, acc);
                acc = fmaf(sh[wid][q * 4 + 3], ev.w, acc);
            }
            float s = 2.f * acc - g_enorm2[code];
            unsigned u = __float_as_uint(s);
            u = (u & 0x80000000u) ? ~u : (u | 0x80000000u);
            unsigned long long key =
                ((unsigned long long)u << 32) | (unsigned)(0xFFFFFFFFu - (unsigned)code);
            best = (key > best) ? key : best;
        }
    }
#pragma unroll
    for (int off = 16; off; off >>= 1) {
        unsigned long long o = __shfl_xor_sync(0xffffffffu, best, off);
        best = (o > best) ? o : best;
    }
    // every lane holds the winning key -> fused masked gather + code emit
    int code = (int)(0xFFFFFFFFu - (unsigned)(best & 0xFFFFFFFFull));
    int msk = (attn[token] == 1);
    const float* e = &g_embed[(size_t)code * VQd];
    g_esel[(size_t)token * VQd + lane] = msk ? e[lane] : 0.f;
    g_esel[(size_t)token * VQd + lane + 32] = msk ? e[lane + 32] : 0.f;
    if (write_codes && lane == 0)
        out_codes[token] = msk ? (float)code : 0.f;
}

// ---------------- host launcher ----------------
extern "C" void kernel_launch(void* const* d_in, const int* in_sizes, int n_in,
                              void* d_out, int out_size)
{
    const float* h_in     = (const float*)d_in[0];
    const int*   attn     = (const int*)  d_in[1];
    const float* proj_w   = (const float*)d_in[2];
    const float* proj_b   = (const float*)d_in[3];
    const float* inv_w    = (const float*)d_in[4];
    const float* inv_b    = (const float*)d_in[5];
    const float* mlp_w_in = (const float*)d_in[6];
    const float* mlp_b_in = (const float*)d_in[7];
    const float* w_mid    = (const float*)d_in[8];
    const float* b_mid    = (const float*)d_in[9];
    const float* w_out    = (const float*)d_in[10];
    const float* b_out    = (const float*)d_in[11];
    const float* gamma    = (const float*)d_in[12];
    const float* beta     = (const float*)d_in[13];
    float* out = (float*)d_out;

    void *px_, *py_, *pes_, *ph_;
    cudaGetSymbolAddress(&px_, g_x);
    cudaGetSymbolAddress(&py_, g_y);
    cudaGetSymbolAddress(&pes_, g_esel);
    cudaGetSymbolAddress(&ph_, g_h);
    float* px = (float*)px_;
    float* py = (float*)py_;
    float* pes = (float*)pes_;
    float* ph = (float*)ph_;

    const int COARSE_SMEM = (2 * 128 * CPITCH + 128) * 4;
    cudaFuncSetAttribute(coarse_kernel,
                         cudaFuncAttributeMaxDynamicSharedMemorySize, COARSE_SMEM);

    // 0) zero all per-layer BN stats once
    zero_all_stats_kernel<<<(N_MID * 2 * HID + 255) / 256, 256>>>();

    // 1) codebook MLP (fp32, chains bit-identical; stats fused into GEMM epilogue)
    layer0_kernel<<<dim3(4, 256), 256>>>(mlp_w_in, mlp_b_in, gamma, beta, px);
    for (int i = 0; i < N_MID; i++) {
        gemm128_nt<<<dim3(HID / 128, K_CB / 128), 256>>>(
            px, w_mid + (size_t)i * HID * HID, b_mid + i * HID, py, K_CB, HID, HID, i);
        bn_norm_relu_kernel<<<(K_CB * HID / 4) / 1024, 256>>>(
            py, gamma + (i + 1) * HID, beta + (i + 1) * HID, px, i);
    }
    gemm64_nt<<<dim3(1, K_CB / 64), 256>>>(px, w_out, b_out, py, K_CB, VQd, HID);
    embed_norm_kernel<<<K_CB / 8, 256>>>(py);

    // 2) hidden projection + L2 normalize
    hproj_kernel<<<dim3(Tt / 128, Bb), 256>>>(h_in, proj_w, proj_b, ph);

    // 3) certified two-pass argmax + fused gather
    coarse_kernel<<<NTOK / 128, 256, COARSE_SMEM>>>();
    int write_codes = (out_size >= NTOK * Dd + NTOK) ? 1 : 0;
    rescore_gather_kernel<<<NTOK / 8, 256>>>(attn, out + (size_t)NTOK * Dd, write_codes);

    // 4) inverse projection straight into d_out (no stats)
    gemm128_nt<<<dim3(Dd / 128, NTOK / 128), 256>>>(
        pes, inv_w, inv_b, out, NTOK, Dd, VQd, -1);
}

// round 16
// speedup vs baseline: 1.6959x; 1.0331x over previous
#include <cuda_runtime.h>
#include <cuda_bf16.h>
#include <stdint.h>

// Problem constants
#define K_CB   4096
#define HID    1024
#define VQd    64
#define Dd     768
#define Bb     8
#define Tt     2048
#define NTOK   (Bb*Tt)
#define L2b    12
#define N_MID  4
#define EPS_N  1e-6f
#define EPS_BN 1e-5f

#define CCAP   256
#define CTH    0.03f
#define CPITCH 68
#define TOKB   64            // tokens per coarse CTA (was 128)

// ---------------- scratch (device globals) ----------------
__device__ float g_x[K_CB * HID];
__device__ float g_y[K_CB * HID];
__device__ float g_embed[K_CB * VQd];
__device__ float g_enorm2[K_CB];
__device__ float g_h[NTOK * VQd];
__device__ float g_esel[NTOK * VQd];
__device__ float g_stats[N_MID * 2 * HID];
__device__ int g_ccnt[NTOK];
__device__ int g_cand[(size_t)NTOK * CCAP];

// ---------------- helpers ----------------
static __device__ __forceinline__ void mma_tf32(float* c, const uint32_t* a,
                                                const uint32_t* b) {
    asm volatile(
        "mma.sync.aligned.m16n8k8.row.col.f32.tf32.tf32.f32 "
        "{%0,%1,%2,%3}, {%4,%5,%6,%7}, {%8,%9}, {%0,%1,%2,%3};"
        : "+f"(c[0]), "+f"(c[1]), "+f"(c[2]), "+f"(c[3])
        : "r"(a[0]), "r"(a[1]), "r"(a[2]), "r"(a[3]), "r"(b[0]), "r"(b[1]));
}
static __device__ __forceinline__ unsigned fmap(float s) {
    unsigned u = __float_as_uint(s);
    return (u & 0x80000000u) ? ~u : (u | 0x80000000u);
}
static __device__ __forceinline__ float funmap(unsigned v) {
    unsigned u = (v & 0x80000000u) ? (v ^ 0x80000000u) : ~v;
    return __uint_as_float(u);
}

// ---------------- small utility kernels ----------------
__global__ void zero_all_stats_kernel() {
    int i = blockIdx.x * 256 + threadIdx.x;
    if (i < N_MID * 2 * HID) g_stats[i] = 0.f;
}

// ---------------- layer 0 (R1-proven) ----------------
__global__ __launch_bounds__(256) void layer0_kernel(
    const float* __restrict__ W, const float* __restrict__ bias,
    const float* __restrict__ gamma, const float* __restrict__ beta,
    float* __restrict__ X)
{
    int f = blockIdx.x * 256 + threadIdx.x;
    int k0 = blockIdx.y * 16;
    float w[L2b];
    float sw = 0.f, sw2 = 0.f;
#pragma unroll
    for (int j = 0; j < L2b; j++) {
        w[j] = W[f * L2b + j];
        sw += w[j]; sw2 += w[j] * w[j];
    }
    float b = bias[f];
    float m = b + 0.5f * sw;
    float v = 0.25f * sw2;
    float rstd = rsqrtf(v + EPS_BN);
    float ga = gamma[f] * rstd;
    float be = beta[f];
#pragma unroll 4
    for (int kk = 0; kk < 16; kk++) {
        int k = k0 + kk;
        float y = b;
#pragma unroll
        for (int j = 0; j < L2b; j++)
            if ((k >> (11 - j)) & 1) y += w[j];
        float o = (y - m) * ga + be;
        X[k * HID + f] = fmaxf(o, 0.f);
    }
}

// ---------------- BN normalize + ReLU (R9-proven) ----------------
__global__ __launch_bounds__(256) void bn_norm_relu_kernel(
    const float* __restrict__ Y, const float* __restrict__ gamma,
    const float* __restrict__ beta, float* __restrict__ X, int layer)
{
    const float* st = &g_stats[layer * 2 * HID];
    int base = blockIdx.x * 1024 + threadIdx.x;
#pragma unroll
    for (int u = 0; u < 4; u++) {
        int i4 = base + u * 256;
        int f0 = (i4 * 4) & (HID - 1);
        float4 y = ((const float4*)Y)[i4];
        float yv[4] = { y.x, y.y, y.z, y.w };
        float out[4];
#pragma unroll
        for (int j = 0; j < 4; j++) {
            int f = f0 + j;
            float m = st[f] * (1.f / K_CB);
            float var = st[HID + f] * (1.f / K_CB) - m * m;
            float o = (yv[j] - m) * rsqrtf(var + EPS_BN) * gamma[f] + beta[f];
            out[j] = fmaxf(o, 0.f);
        }
        ((float4*)X)[i4] = make_float4(out[0], out[1], out[2], out[3]);
    }
}

// ---------------- fp32 NT GEMM, double-buffered BK=16 + fused BN stats (R9-proven) ----------------
__global__ __launch_bounds__(256, 2) void gemm128_nt(
    const float* __restrict__ A, const float* __restrict__ B,
    const float* __restrict__ bias, float* __restrict__ C,
    int M, int N, int K, int layer)
{
    __shared__ float As[2][16][132];
    __shared__ float Bs[2][16][132];
    const int tid = threadIdx.x;
    const int tx = tid & 15, ty = tid >> 4;
    const int m0 = blockIdx.y * 128, n0 = blockIdx.x * 128;
    const int lr = tid >> 1;
    const int lc = (tid & 1) << 3;
    const float* Ag = A + (size_t)(m0 + lr) * K + lc;
    const float* Bg = B + (size_t)(n0 + lr) * K + lc;

    float acc[8][8];
#pragma unroll
    for (int i = 0; i < 8; i++)
#pragma unroll
        for (int j = 0; j < 8; j++) acc[i][j] = 0.f;

    float4 ra0 = *(const float4*)(Ag);
    float4 ra1 = *(const float4*)(Ag + 4);
    float4 rb0 = *(const float4*)(Bg);
    float4 rb1 = *(const float4*)(Bg + 4);

    const int NC = K >> 4;
    for (int c = 0; c < NC; c++) {
        const int s = c & 1;
        As[s][lc + 0][lr] = ra0.x; As[s][lc + 1][lr] = ra0.y;
        As[s][lc + 2][lr] = ra0.z; As[s][lc + 3][lr] = ra0.w;
        As[s][lc + 4][lr] = ra1.x; As[s][lc + 5][lr] = ra1.y;
        As[s][lc + 6][lr] = ra1.z; As[s][lc + 7][lr] = ra1.w;
        Bs[s][lc + 0][lr] = rb0.x; Bs[s][lc + 1][lr] = rb0.y;
        Bs[s][lc + 2][lr] = rb0.z; Bs[s][lc + 3][lr] = rb0.w;
        Bs[s][lc + 4][lr] = rb1.x; Bs[s][lc + 5][lr] = rb1.y;
        Bs[s][lc + 6][lr] = rb1.z; Bs[s][lc + 7][lr] = rb1.w;
        __syncthreads();
        if (c + 1 < NC) {
            const int kn = (c + 1) << 4;
            ra0 = *(const float4*)(Ag + kn);
            ra1 = *(const float4*)(Ag + kn + 4);
            rb0 = *(const float4*)(Bg + kn);
            rb1 = *(const float4*)(Bg + kn + 4);
        }
#pragma unroll
        for (int kk = 0; kk < 16; kk++) {
            float ar[8], br[8];
            *(float4*)&ar[0] = *(const float4*)&As[s][kk][ty * 4];
            *(float4*)&ar[4] = *(const float4*)&As[s][kk][64 + ty * 4];
            *(float4*)&br[0] = *(const float4*)&Bs[s][kk][tx * 4];
            *(float4*)&br[4] = *(const float4*)&Bs[s][kk][64 + tx * 4];
#pragma unroll
            for (int i = 0; i < 8; i++)
#pragma unroll
                for (int j = 0; j < 8; j++)
                    acc[i][j] = fmaf(ar[i], br[j], acc[i][j]);
        }
    }

    float cs[8], cs2[8];
#pragma unroll
    for (int j8 = 0; j8 < 8; j8++) { cs[j8] = 0.f; cs2[j8] = 0.f; }

#pragma unroll
    for (int ih = 0; ih < 2; ih++) {
#pragma unroll
        for (int i = 0; i < 4; i++) {
            int r = m0 + ih * 64 + ty * 4 + i;
            float* Crow = C + (size_t)r * N + n0;
#pragma unroll
            for (int jh = 0; jh < 2; jh++) {
                int cb = jh * 64 + tx * 4;
                float4 v;
                v.x = acc[ih * 4 + i][jh * 4 + 0] + bias[n0 + cb + 0];
                v.y = acc[ih * 4 + i][jh * 4 + 1] + bias[n0 + cb + 1];
                v.z = acc[ih * 4 + i][jh * 4 + 2] + bias[n0 + cb + 2];
                v.w = acc[ih * 4 + i][jh * 4 + 3] + bias[n0 + cb + 3];
                *(float4*)(Crow + cb) = v;
                if (layer >= 0) {
                    cs[jh * 4 + 0] += v.x;  cs2[jh * 4 + 0] += v.x * v.x;
                    cs[jh * 4 + 1] += v.y;  cs2[jh * 4 + 1] += v.y * v.y;
                    cs[jh * 4 + 2] += v.z;  cs2[jh * 4 + 2] += v.z * v.z;
                    cs[jh * 4 + 3] += v.w;  cs2[jh * 4 + 3] += v.w * v.w;
                }
            }
        }
    }
    if (layer >= 0) {
        __syncthreads();
        float* sst = &As[0][0][0];
        if (tid < 256) sst[tid] = 0.f;
        __syncthreads();
#pragma unroll
        for (int jh = 0; jh < 2; jh++)
#pragma unroll
            for (int j = 0; j < 4; j++) {
                int cl = jh * 64 + tx * 4 + j;
                atomicAdd(&sst[cl], cs[jh * 4 + j]);
                atomicAdd(&sst[128 + cl], cs2[jh * 4 + j]);
            }
        __syncthreads();
        if (tid < 128) {
            float* gs = &g_stats[layer * 2 * HID];
            atomicAdd(&gs[n0 + tid], sst[tid]);
            atomicAdd(&gs[HID + n0 + tid], sst[128 + tid]);
        }
    }
}

// ---------------- 64x64 NT GEMM, double-buffered BK=16 (R14-proven) ----------------
__global__ __launch_bounds__(256) void gemm64_nt(
    const float* __restrict__ A, const float* __restrict__ B,
    const float* __restrict__ bias, float* __restrict__ C,
    int M, int N, int K)
{
    __shared__ float As[2][16][68];
    __shared__ float Bs[2][16][68];
    const int tid = threadIdx.x;
    const int tx = tid & 15, ty = tid >> 4;
    const int m0 = blockIdx.y * 64, n0 = blockIdx.x * 64;
    float acc[4][4];
#pragma unroll
    for (int i = 0; i < 4; i++)
#pragma unroll
        for (int j = 0; j < 4; j++) acc[i][j] = 0.f;

    const int half = tid >> 7;
    const int lt = tid & 127;
    const int lr = lt >> 1;
    const int lcv = (lt & 1) << 3;
    const float* G = half ? (B + (size_t)(n0 + lr) * K + lcv)
                          : (A + (size_t)(m0 + lr) * K + lcv);

    float4 r0 = *(const float4*)(G);
    float4 r1 = *(const float4*)(G + 4);

    const int NC = K >> 4;
    for (int c = 0; c < NC; c++) {
        const int s = c & 1;
        float (*S)[68] = half ? Bs[s] : As[s];
        S[lcv + 0][lr] = r0.x; S[lcv + 1][lr] = r0.y;
        S[lcv + 2][lr] = r0.z; S[lcv + 3][lr] = r0.w;
        S[lcv + 4][lr] = r1.x; S[lcv + 5][lr] = r1.y;
        S[lcv + 6][lr] = r1.z; S[lcv + 7][lr] = r1.w;
        __syncthreads();
        if (c + 1 < NC) {
            const int kn = (c + 1) << 4;
            r0 = *(const float4*)(G + kn);
            r1 = *(const float4*)(G + kn + 4);
        }
#pragma unroll
        for (int kk = 0; kk < 16; kk++) {
            float ar[4], br[4];
            *(float4*)&ar[0] = *(const float4*)&As[s][kk][ty * 4];
            *(float4*)&br[0] = *(const float4*)&Bs[s][kk][tx * 4];
#pragma unroll
            for (int i = 0; i < 4; i++)
#pragma unroll
                for (int j = 0; j < 4; j++)
                    acc[i][j] = fmaf(ar[i], br[j], acc[i][j]);
        }
    }
#pragma unroll
    for (int i = 0; i < 4; i++) {
        int r = m0 + ty * 4 + i;
        float4 v;
        v.x = acc[i][0] + bias[n0 + tx * 4 + 0];
        v.y = acc[i][1] + bias[n0 + tx * 4 + 1];
        v.z = acc[i][2] + bias[n0 + tx * 4 + 2];
        v.w = acc[i][3] + bias[n0 + tx * 4 + 3];
        *(float4*)(C + (size_t)r * N + n0 + tx * 4) = v;
    }
}

// ---------------- embed L2 norm + ||e||^2 (R1-proven) ----------------
__global__ __launch_bounds__(256) void embed_norm_kernel(const float* __restrict__ Eraw)
{
    int row = blockIdx.x * 8 + (threadIdx.x >> 5);
    int lane = threadIdx.x & 31;
    float v0 = Eraw[row * VQd + lane];
    float v1 = Eraw[row * VQd + 32 + lane];
    float s = v0 * v0 + v1 * v1;
#pragma unroll
    for (int off = 16; off; off >>= 1) s += __shfl_xor_sync(0xffffffffu, s, off);
    float norm = sqrtf(s);
    float sc = 1.f / (norm + EPS_N);
    g_embed[row * VQd + lane] = v0 * sc;
    g_embed[row * VQd + 32 + lane] = v1 * sc;
    if (lane == 0) g_enorm2[row] = s * sc * sc;
}

// ---------------- hidden projection + L2 normalize (R1-proven) ----------------
__global__ __launch_bounds__(256) void hproj_kernel(
    const float* __restrict__ Hin, const float* __restrict__ Pw,
    const float* __restrict__ Pb, float* __restrict__ Hout)
{
    __shared__ float Ash[32][132];
    __shared__ float Wsh[32][65];
    const int tid = threadIdx.x;
    const int b = blockIdx.y;
    const int t0 = blockIdx.x * 128;
    const int tx = tid & 15, ty = tid >> 4;
    float acc[8][4];
#pragma unroll
    for (int i = 0; i < 8; i++)
#pragma unroll
        for (int j = 0; j < 4; j++) acc[i][j] = 0.f;

    const int lt = tid & 127;
    const int ldr = tid >> 7;
    const int wv = tid >> 5;
    const int wd = tid & 31;

    for (int d0 = 0; d0 < Dd; d0 += 32) {
#pragma unroll
        for (int dd = ldr; dd < 32; dd += 2)
            Ash[dd][lt] = Hin[(size_t)(b * Dd + d0 + dd) * Tt + t0 + lt];
#pragma unroll
        for (int vv = wv; vv < 64; vv += 8)
            Wsh[wd][vv] = Pw[vv * Dd + d0 + wd];
        __syncthreads();
#pragma unroll
        for (int kk = 0; kk < 32; kk++) {
            float ar[8], br[4];
            *(float4*)&ar[0] = *(const float4*)&Ash[kk][ty * 4];
            *(float4*)&ar[4] = *(const float4*)&Ash[kk][64 + ty * 4];
#pragma unroll
            for (int j = 0; j < 4; j++) br[j] = Wsh[kk][tx * 4 + j];
#pragma unroll
            for (int i = 0; i < 8; i++)
#pragma unroll
                for (int j = 0; j < 4; j++)
                    acc[i][j] = fmaf(ar[i], br[j], acc[i][j]);
        }
        __syncthreads();
    }
    float bb[4];
#pragma unroll
    for (int j = 0; j < 4; j++) bb[j] = Pb[tx * 4 + j];
#pragma unroll
    for (int i = 0; i < 8; i++) {
        float hv[4]; float ssq = 0.f;
#pragma unroll
        for (int j = 0; j < 4; j++) { hv[j] = acc[i][j] + bb[j]; ssq += hv[j] * hv[j]; }
#pragma unroll
        for (int off = 8; off; off >>= 1) ssq += __shfl_xor_sync(0xffffffffu, ssq, off, 16);
        float sc = 1.f / (sqrtf(ssq) + EPS_N);
        int t = t0 + ((i < 4) ? ty * 4 + i : 64 + ty * 4 + (i - 4));
        float4 o = make_float4(hv[0] * sc, hv[1] * sc, hv[2] * sc, hv[3] * sc);
        *(float4*)&Hout[(size_t)(b * Tt + t) * VQd + tx * 4] = o;
    }
}

// ---------------- coarse tf32 score pass, 64 tokens/CTA (2 CTAs/SM) ----------------
// Per-token semantics identical to the proven 128-row kernel: every token scans all
// 4096 codes inside one CTA with a per-token running max threshold.
__global__ __launch_bounds__(256, 2) void coarse_kernel()
{
    extern __shared__ float smc[];
    float* sA = smc;                           // 64 x CPITCH
    float* sB = smc + TOKB * CPITCH;           // 128 x CPITCH
    float* e2sm = smc + (TOKB + 128) * CPITCH; // 128
    __shared__ unsigned smax[TOKB];
    __shared__ int cnt[TOKB];

    const int tid = threadIdx.x;
    const int lane = tid & 31, wid = tid >> 5;
    const int wm = wid >> 2, wn = wid & 3;     // wm in {0,1} -> 32 rows each
    const int g = lane >> 2, tig = lane & 3;
    const int m0 = blockIdx.x * TOKB;

    for (int i = tid; i < TOKB * 16; i += 256) {
        int r = i >> 4, q = i & 15;
        *(float4*)&sA[r * CPITCH + q * 4] = *(const float4*)&g_h[(size_t)(m0 + r) * VQd + q * 4];
    }
    if (tid < TOKB) { smax[tid] = 0u; cnt[tid] = 0; }
    __syncthreads();

    for (int ch = 0; ch < 32; ch++) {
        const int n0 = ch * 128;
        for (int i = tid; i < 2048; i += 256) {
            int r = i >> 4, q = i & 15;
            *(float4*)&sB[r * CPITCH + q * 4] = *(const float4*)&g_embed[(size_t)(n0 + r) * VQd + q * 4];
        }
        if (tid < 128) e2sm[tid] = g_enorm2[n0 + tid];
        __syncthreads();

        float acc[2][4][4];
#pragma unroll
        for (int mt = 0; mt < 2; mt++)
#pragma unroll
            for (int nt = 0; nt < 4; nt++)
#pragma unroll
                for (int q = 0; q < 4; q++) acc[mt][nt][q] = 0.f;

#pragma unroll
        for (int ks = 0; ks < 8; ks++) {
            const int kb = ks * 8;
            uint32_t a[2][4];
#pragma unroll
            for (int mt = 0; mt < 2; mt++) {
                const uint32_t* pa = (const uint32_t*)&sA[(wm * 32 + mt * 16 + g) * CPITCH + kb + tig];
                a[mt][0] = pa[0];
                a[mt][1] = pa[8 * CPITCH];
                a[mt][2] = pa[4];
                a[mt][3] = pa[8 * CPITCH + 4];
            }
            uint32_t b[4][2];
#pragma unroll
            for (int nt = 0; nt < 4; nt++) {
                const uint32_t* pb = (const uint32_t*)&sB[(wn * 32 + nt * 8 + g) * CPITCH + kb + tig];
                b[nt][0] = pb[0];
                b[nt][1] = pb[4];
            }
#pragma unroll
            for (int mt = 0; mt < 2; mt++)
#pragma unroll
                for (int nt = 0; nt < 4; nt++)
                    mma_tf32(acc[mt][nt], a[mt], b[nt]);
        }

        float rmax[2][2];
#pragma unroll
        for (int mt = 0; mt < 2; mt++) {
            rmax[mt][0] = -3.4e38f; rmax[mt][1] = -3.4e38f;
#pragma unroll
            for (int nt = 0; nt < 4; nt++) {
                int col0 = wn * 32 + nt * 8 + 2 * tig;
                float e20 = e2sm[col0], e21 = e2sm[col0 + 1];
                float s0 = 2.f * acc[mt][nt][0] - e20;
                float s1 = 2.f * acc[mt][nt][1] - e21;
                float s2 = 2.f * acc[mt][nt][2] - e20;
                float s3 = 2.f * acc[mt][nt][3] - e21;
                rmax[mt][0] = fmaxf(rmax[mt][0], fmaxf(s0, s1));
                rmax[mt][1] = fmaxf(rmax[mt][1], fmaxf(s2, s3));
            }
        }
#pragma unroll
        for (int off = 1; off <= 2; off <<= 1)
#pragma unroll
            for (int mt = 0; mt < 2; mt++)
#pragma unroll
                for (int h = 0; h < 2; h++)
                    rmax[mt][h] = fmaxf(rmax[mt][h], __shfl_xor_sync(0xffffffffu, rmax[mt][h], off));
        if (tig == 0) {
#pragma unroll
            for (int mt = 0; mt < 2; mt++) {
                atomicMax(&smax[wm * 32 + mt * 16 + g], fmap(rmax[mt][0]));
                atomicMax(&smax[wm * 32 + mt * 16 + g + 8], fmap(rmax[mt][1]));
            }
        }
        __syncthreads();

#pragma unroll
        for (int mt = 0; mt < 2; mt++) {
            int rr0 = wm * 32 + mt * 16 + g;
            float th0 = funmap(smax[rr0]) - CTH;
            float th1 = funmap(smax[rr0 + 8]) - CTH;
#pragma unroll
            for (int nt = 0; nt < 4; nt++) {
                int col0 = wn * 32 + nt * 8 + 2 * tig;
                float e20 = e2sm[col0], e21 = e2sm[col0 + 1];
                float s0 = 2.f * acc[mt][nt][0] - e20;
                float s1 = 2.f * acc[mt][nt][1] - e21;
                float s2 = 2.f * acc[mt][nt][2] - e20;
                float s3 = 2.f * acc[mt][nt][3] - e21;
                if (s0 >= th0) { int p = atomicAdd(&cnt[rr0], 1); if (p < CCAP) g_cand[(size_t)(m0 + rr0) * CCAP + p] = n0 + col0; }
                if (s1 >= th0) { int p = atomicAdd(&cnt[rr0], 1); if (p < CCAP) g_cand[(size_t)(m0 + rr0) * CCAP + p] = n0 + col0 + 1; }
                if (s2 >= th1) { int p = atomicAdd(&cnt[rr0 + 8], 1); if (p < CCAP) g_cand[(size_t)(m0 + rr0 + 8) * CCAP + p] = n0 + col0; }
                if (s3 >= th1) { int p = atomicAdd(&cnt[rr0 + 8], 1); if (p < CCAP) g_cand[(size_t)(m0 + rr0 + 8) * CCAP + p] = n0 + col0 + 1; }
            }
        }
        __syncthreads();
    }
    if (tid < TOKB) g_ccnt[m0 + tid] = cnt[tid];
}

// ---------------- exact rescore + fused gather (R14-proven) ----------------
__global__ __launch_bounds__(256) void rescore_gather_kernel(
    const int* __restrict__ attn, float* __restrict__ out_codes, int write_codes)
{
    __shared__ float sh[8][VQd];
    const int tid = threadIdx.x;
    const int lane = tid & 31, wid = tid >> 5;
    const int token = blockIdx.x * 8 + wid;

    sh[wid][lane] = g_h[(size_t)token * VQd + lane];
    sh[wid][lane + 32] = g_h[(size_t)token * VQd + lane + 32];
    __syncwarp();

    int cnt = g_ccnt[token];
    unsigned long long best = 0ull;

    if (cnt > 0 && cnt <= CCAP) {
        for (int ci = lane; ci < cnt; ci += 32) {
            int code = g_cand[(size_t)token * CCAP + ci];
            float acc = 0.f;
            const float* e = &g_embed[(size_t)code * VQd];
#pragma unroll
            for (int q = 0; q < 16; q++) {
                float4 ev = *(const float4*)&e[q * 4];
                acc = fmaf(sh[wid][q * 4 + 0], ev.x, acc);
                acc = fmaf(sh[wid][q * 4 + 1], ev.y, acc);
                acc = fmaf(sh[wid][q * 4 + 2], ev.z, acc);
                acc = fmaf(sh[wid][q * 4 + 3], ev.w, acc);
            }
            float s = 2.f * acc - g_enorm2[code];
            unsigned u = __float_as_uint(s);
            u = (u & 0x80000000u) ? ~u : (u | 0x80000000u);
            unsigned long long key =
                ((unsigned long long)u << 32) | (unsigned)(0xFFFFFFFFu - (unsigned)code);
            best = (key > best) ? key : best;
        }
    } else {
        for (int code = lane; code < K_CB; code += 32) {
            float acc = 0.f;
            const float* e = &g_embed[(size_t)code * VQd];
#pragma unroll
            for (int q = 0; q < 16; q++) {
                float4 ev = *(const float4*)&e[q * 4];
                acc = fmaf(sh[wid][q * 4 + 0], ev.x, acc);
                acc = fmaf(sh[wid][q * 4 + 1], ev.y, acc);
                acc = fmaf(sh[wid][q * 4 + 2], ev.z, acc);
                acc = fmaf(sh[wid][q * 4 + 3], ev.w, acc);
            }
            float s = 2.f * acc - g_enorm2[code];
            unsigned u = __float_as_uint(s);
            u = (u & 0x80000000u) ? ~u : (u | 0x80000000u);
            unsigned long long key =
                ((unsigned long long)u << 32) | (unsigned)(0xFFFFFFFFu - (unsigned)code);
            best = (key > best) ? key : best;
        }
    }
#pragma unroll
    for (int off = 16; off; off >>= 1) {
        unsigned long long o = __shfl_xor_sync(0xffffffffu, best, off);
        best = (o > best) ? o : best;
    }
    int code = (int)(0xFFFFFFFFu - (unsigned)(best & 0xFFFFFFFFull));
    int msk = (attn[token] == 1);
    const float* e = &g_embed[(size_t)code * VQd];
    g_esel[(size_t)token * VQd + lane] = msk ? e[lane] : 0.f;
    g_esel[(size_t)token * VQd + lane + 32] = msk ? e[lane + 32] : 0.f;
    if (write_codes && lane == 0)
        out_codes[token] = msk ? (float)code : 0.f;
}

// ---------------- host launcher ----------------
extern "C" void kernel_launch(void* const* d_in, const int* in_sizes, int n_in,
                              void* d_out, int out_size)
{
    const float* h_in     = (const float*)d_in[0];
    const int*   attn     = (const int*)  d_in[1];
    const float* proj_w   = (const float*)d_in[2];
    const float* proj_b   = (const float*)d_in[3];
    const float* inv_w    = (const float*)d_in[4];
    const float* inv_b    = (const float*)d_in[5];
    const float* mlp_w_in = (const float*)d_in[6];
    const float* mlp_b_in = (const float*)d_in[7];
    const float* w_mid    = (const float*)d_in[8];
    const float* b_mid    = (const float*)d_in[9];
    const float* w_out    = (const float*)d_in[10];
    const float* b_out    = (const float*)d_in[11];
    const float* gamma    = (const float*)d_in[12];
    const float* beta     = (const float*)d_in[13];
    float* out = (float*)d_out;

    void *px_, *py_, *pes_, *ph_;
    cudaGetSymbolAddress(&px_, g_x);
    cudaGetSymbolAddress(&py_, g_y);
    cudaGetSymbolAddress(&pes_, g_esel);
    cudaGetSymbolAddress(&ph_, g_h);
    float* px = (float*)px_;
    float* py = (float*)py_;
    float* pes = (float*)pes_;
    float* ph = (float*)ph_;

    const int COARSE_SMEM = ((TOKB + 128) * CPITCH + 128) * 4;   // ~52.7 KB
    cudaFuncSetAttribute(coarse_kernel,
                         cudaFuncAttributeMaxDynamicSharedMemorySize, COARSE_SMEM);

    // 0) zero all per-layer BN stats once
    zero_all_stats_kernel<<<(N_MID * 2 * HID + 255) / 256, 256>>>();

    // 1) codebook MLP (fp32, chains bit-identical; stats fused into GEMM epilogue)
    layer0_kernel<<<dim3(4, 256), 256>>>(mlp_w_in, mlp_b_in, gamma, beta, px);
    for (int i = 0; i < N_MID; i++) {
        gemm128_nt<<<dim3(HID / 128, K_CB / 128), 256>>>(
            px, w_mid + (size_t)i * HID * HID, b_mid + i * HID, py, K_CB, HID, HID, i);
        bn_norm_relu_kernel<<<(K_CB * HID / 4) / 1024, 256>>>(
            py, gamma + (i + 1) * HID, beta + (i + 1) * HID, px, i);
    }
    gemm64_nt<<<dim3(1, K_CB / 64), 256>>>(px, w_out, b_out, py, K_CB, VQd, HID);
    embed_norm_kernel<<<K_CB / 8, 256>>>(py);

    // 2) hidden projection + L2 normalize
    hproj_kernel<<<dim3(Tt / 128, Bb), 256>>>(h_in, proj_w, proj_b, ph);

    // 3) certified two-pass argmax + fused gather (coarse at 2 CTAs/SM)
    coarse_kernel<<<NTOK / TOKB, 256, COARSE_SMEM>>>();
    int write_codes = (out_size >= NTOK * Dd + NTOK) ? 1 : 0;
    rescore_gather_kernel<<<NTOK / 8, 256>>>(attn, out + (size_t)NTOK * Dd, write_codes);

    // 4) inverse projection straight into d_out (no stats)
    gemm128_nt<<<dim3(Dd / 128, NTOK / 128), 256>>>(
        pes, inv_w, inv_b, out, NTOK, Dd, VQd, -1);
}